// round 2
// baseline (speedup 1.0000x reference)
#include <cuda_runtime.h>
#include <cstdint>

#define NN      100000
#define EE      800000
#define E3N     400000
#define NODE_IN 13
#define DIM     128
#define DIMF    256

// ---------------- scratch (static __device__; no allocation allowed) -------
__device__ float g_h1  [(size_t)NN * DIMF];   // lin_node intermediate
__device__ float g_hA  [(size_t)NN * DIM];    // node features ping
__device__ float g_hB  [(size_t)NN * DIM];    // node features pong
__device__ float g_hshd[(size_t)NN * DIMF];   // [h@Wsrc | h@Wdst] per node
__device__ float g_aggr[(size_t)NN * DIM];    // scatter-mean accumulator
__device__ float g_inv1[NN];
__device__ float g_inv2[NN];
__device__ float g_stat1[32];
__device__ float g_stat2[2 * DIMF];
__device__ float g_W1f[NODE_IN * DIMF];
__device__ float g_b1f[DIMF];
__device__ float g_W2f[DIMF * DIM];
__device__ float g_b2f[DIM];

// vector global reduction: one 16B red instead of 4 scalar atomics
__device__ __forceinline__ void red_add_v4(float* p, float4 v)
{
#if __CUDA_ARCH__ >= 900
    asm volatile("red.global.add.v4.f32 [%0], {%1, %2, %3, %4};"
                 :: "l"(p), "f"(v.x), "f"(v.y), "f"(v.z), "f"(v.w) : "memory");
#else
    atomicAdd(p + 0, v.x); atomicAdd(p + 1, v.y);
    atomicAdd(p + 2, v.z); atomicAdd(p + 3, v.w);
#endif
}

// ---------------- column stats of x (13 cols) ------------------------------
__global__ void stats13_kernel(const float* __restrict__ x, float* __restrict__ stat)
{
    float ls[NODE_IN], lq[NODE_IN];
#pragma unroll
    for (int c = 0; c < NODE_IN; c++) { ls[c] = 0.f; lq[c] = 0.f; }
    int stride = gridDim.x * blockDim.x;
    for (int r = blockIdx.x * blockDim.x + threadIdx.x; r < NN; r += stride) {
#pragma unroll
        for (int c = 0; c < NODE_IN; c++) {
            float v = x[(size_t)r * NODE_IN + c];
            ls[c] += v; lq[c] += v * v;
        }
    }
    __shared__ float ss[2 * NODE_IN];
    if (threadIdx.x < 2 * NODE_IN) ss[threadIdx.x] = 0.f;
    __syncthreads();
#pragma unroll
    for (int c = 0; c < NODE_IN; c++) {
        atomicAdd(&ss[c], ls[c]);
        atomicAdd(&ss[NODE_IN + c], lq[c]);
    }
    __syncthreads();
    if (threadIdx.x < 2 * NODE_IN) atomicAdd(&stat[threadIdx.x], ss[threadIdx.x]);
}

// ---------------- fold bn1 into lin1 ---------------------------------------
__global__ void fold1_kernel(const float* __restrict__ stat,
                             const float* __restrict__ g, const float* __restrict__ b,
                             const float* __restrict__ W1, const float* __restrict__ b1,
                             float* __restrict__ W1f, float* __restrict__ b1f)
{
    __shared__ float alpha[NODE_IN], beta[NODE_IN];
    int t = threadIdx.x;  // 0..255 = output column
    if (t < NODE_IN) {
        float m = stat[t] * (1.0f / NN);
        float v = stat[NODE_IN + t] * (1.0f / NN) - m * m;
        float a = g[t] * rsqrtf(v + 1e-5f);
        alpha[t] = a;
        beta[t]  = b[t] - m * a;
    }
    __syncthreads();
    float acc = b1[t];
#pragma unroll
    for (int k = 0; k < NODE_IN; k++) {
        float w = W1[k * DIMF + t];
        W1f[k * DIMF + t] = alpha[k] * w;
        acc += beta[k] * w;
    }
    b1f[t] = acc;
}

// ---------------- h1 = relu(x @ W1f + b1f) + column stats of h1 -------------
#define H1_ROWS 64
__global__ __launch_bounds__(256)
void h1_kernel(const float* __restrict__ x, const float* __restrict__ W1f,
               const float* __restrict__ b1f, float* __restrict__ h1,
               float* __restrict__ stat2)
{
    __shared__ float xs[H1_ROWS * NODE_IN];
    int t  = threadIdx.x;            // output column 0..255
    int r0 = blockIdx.x * H1_ROWS;
    int nr = min(H1_ROWS, NN - r0);
    for (int i = t; i < nr * NODE_IN; i += 256)
        xs[i] = x[(size_t)r0 * NODE_IN + i];
    __syncthreads();
    float w[NODE_IN];
#pragma unroll
    for (int k = 0; k < NODE_IN; k++) w[k] = W1f[k * DIMF + t];
    float bb = b1f[t];
    float s = 0.f, q = 0.f;
    for (int r = 0; r < nr; r++) {
        float acc = bb;
#pragma unroll
        for (int k = 0; k < NODE_IN; k++) acc = fmaf(xs[r * NODE_IN + k], w[k], acc);
        acc = fmaxf(acc, 0.f);
        h1[(size_t)(r0 + r) * DIMF + t] = acc;
        s += acc; q += acc * acc;
    }
    atomicAdd(&stat2[t], s);
    atomicAdd(&stat2[DIMF + t], q);
}

// ---------------- fold bn2 into lin2 ---------------------------------------
__global__ void fold2_kernel(const float* __restrict__ stat2,
                             const float* __restrict__ g, const float* __restrict__ b,
                             const float* __restrict__ W2, const float* __restrict__ b2,
                             float* __restrict__ W2f, float* __restrict__ b2f)
{
    int k = blockIdx.x;   // 0..255 input channel
    int j = threadIdx.x;  // 0..127 output channel
    __shared__ float al, be;
    if (j == 0) {
        float m = stat2[k] * (1.0f / NN);
        float v = stat2[DIMF + k] * (1.0f / NN) - m * m;
        float a = g[k] * rsqrtf(v + 1e-5f);
        al = a; be = b[k] - m * a;
    }
    __syncthreads();
    float w = W2[k * DIM + j];
    W2f[k * DIM + j] = al * w;
    float contrib = be * w;
    if (k == 0) contrib += b2[j];
    atomicAdd(&b2f[j], contrib);
}

// ---------------- degree counting -------------------------------------------
__global__ void count_kernel(const int* __restrict__ dst, int n, float* __restrict__ cnt)
{
    int i = blockIdx.x * blockDim.x + threadIdx.x;
    if (i < n) atomicAdd(&cnt[dst[i]], 1.0f);
}
__global__ void inv_kernel(float* __restrict__ c, int n)
{
    int i = blockIdx.x * blockDim.x + threadIdx.x;
    if (i < n) c[i] = 1.0f / fmaxf(c[i], 1.0f);
}

// ---------------- tall-skinny SGEMM: C = [relu](A @ B + bias) ---------------
// A: Nrows x K row-major (MODEA=0) or concat [A | A2*scale2] with K=256 (MODEA=1)
// B: K x 128 row-major. C row ldc, column offset colOff.
// DUAL=1: blockIdx.y selects (B0, colOff 0) vs (B1, colOff 128); K=128.
template<int MODEA, int DUAL>
__global__ __launch_bounds__(256, 2)
void sgemm_kernel(const float* __restrict__ A, const float* __restrict__ A2,
                  const float* __restrict__ scale2,
                  const float* __restrict__ B0, const float* __restrict__ B1,
                  const float* __restrict__ bias, int relu,
                  float* __restrict__ C, int ldc, int colOff,
                  int Nrows, int K)
{
    const float* B = B0;
    if (DUAL && blockIdx.y == 1) { B = B1; colOff += 128; }
    __shared__ float As[16][129];
    __shared__ float Bs[16][128];
    int tid  = threadIdx.x;
    int tx   = tid & 15, ty = tid >> 4;
    int brow = blockIdx.x * 128;
    float acc[8][8];
#pragma unroll
    for (int i = 0; i < 8; i++)
#pragma unroll
        for (int j = 0; j < 8; j++) acc[i][j] = 0.f;

    for (int k0 = 0; k0 < K; k0 += 16) {
        __syncthreads();
#pragma unroll
        for (int i = 0; i < 2; i++) {
            int lin = tid + i * 256;
            int r   = lin >> 2;
            int kq  = (lin & 3) << 2;
            int grow = brow + r;
            float4 v = make_float4(0.f, 0.f, 0.f, 0.f);
            if (grow < Nrows) {
                int kk = k0 + kq;
                if (MODEA == 0) {
                    v = *reinterpret_cast<const float4*>(A + (size_t)grow * K + kk);
                } else {
                    if (kk < 128) {
                        v = *reinterpret_cast<const float4*>(A + (size_t)grow * 128 + kk);
                    } else {
                        v = *reinterpret_cast<const float4*>(A2 + (size_t)grow * 128 + (kk - 128));
                        float s = scale2[grow];
                        v.x *= s; v.y *= s; v.z *= s; v.w *= s;
                    }
                }
            }
            As[kq + 0][r] = v.x; As[kq + 1][r] = v.y;
            As[kq + 2][r] = v.z; As[kq + 3][r] = v.w;
        }
#pragma unroll
        for (int i = 0; i < 2; i++) {
            int lin = tid + i * 256;
            int kk  = lin >> 5;
            int c4  = (lin & 31) << 2;
            *reinterpret_cast<float4*>(&Bs[kk][c4]) =
                *reinterpret_cast<const float4*>(B + (size_t)(k0 + kk) * 128 + c4);
        }
        __syncthreads();
#pragma unroll
        for (int kk = 0; kk < 16; kk++) {
            float a[8], bf[8];
#pragma unroll
            for (int i = 0; i < 8; i++) a[i] = As[kk][ty * 8 + i];
#pragma unroll
            for (int j = 0; j < 8; j++) bf[j] = Bs[kk][tx * 8 + j];
#pragma unroll
            for (int i = 0; i < 8; i++)
#pragma unroll
                for (int j = 0; j < 8; j++)
                    acc[i][j] = fmaf(a[i], bf[j], acc[i][j]);
        }
    }
#pragma unroll
    for (int i = 0; i < 8; i++) {
        int grow = brow + ty * 8 + i;
        if (grow >= Nrows) continue;
#pragma unroll
        for (int j = 0; j < 8; j += 4) {
            int col = tx * 8 + j;
            float4 o = make_float4(acc[i][j], acc[i][j+1], acc[i][j+2], acc[i][j+3]);
            if (bias) {
                float4 bb = *reinterpret_cast<const float4*>(bias + col);
                o.x += bb.x; o.y += bb.y; o.z += bb.z; o.w += bb.w;
            }
            if (relu) {
                o.x = fmaxf(o.x, 0.f); o.y = fmaxf(o.y, 0.f);
                o.z = fmaxf(o.z, 0.f); o.w = fmaxf(o.w, 0.f);
            }
            *reinterpret_cast<float4*>(C + (size_t)grow * ldc + colOff + col) = o;
        }
    }
}

// ---------------- edge message + scatter-add --------------------------------
// msg = relu(hs[src] + hd[dst] + ea@We + bm); aggr[dst] += msg (vector red)
template<int EDIM, bool SYM>
__global__ __launch_bounds__(256)
void edge_msg_kernel(const float* __restrict__ hshd,
                     const int* __restrict__ ei,
                     const float* __restrict__ ea, const float* __restrict__ eb,
                     const float* __restrict__ We, const float* __restrict__ bm,
                     float* __restrict__ aggr, int Etot, int Ehalf)
{
    __shared__ float Wes[EDIM * 128];
    __shared__ float bms[128];
    int tid = threadIdx.x;
    for (int i = tid; i < EDIM * 128; i += 256) Wes[i] = We[i];
    if (tid < 128) bms[tid] = bm[tid];
    __syncthreads();
    int e    = (blockIdx.x * 256 + tid) >> 5;
    int lane = tid & 31;
    if (e >= Etot) return;
    int src, dst, eidx;
    if (SYM) {
        src = ei[e];
        if (e < Ehalf) { dst = ei[e + Ehalf]; eidx = e; }
        else           { dst = ei[e - Ehalf]; eidx = e - Ehalf; }
    } else {
        src = ei[e]; dst = ei[Etot + e]; eidx = e;
    }
    float aval = 0.f;
    if (SYM) {
        if (lane < 8)       aval = ea[(size_t)eidx * 8 + lane];
        else if (lane < 16) aval = eb[(size_t)eidx * 8 + (lane - 8)];
    } else {
        if (lane < EDIM)    aval = ea[(size_t)eidx * EDIM + lane];
    }
    int c = lane << 2;
    float4 m = *reinterpret_cast<const float4*>(bms + c);
    float4 a = *reinterpret_cast<const float4*>(hshd + (size_t)src * 256 + c);
    float4 b = *reinterpret_cast<const float4*>(hshd + (size_t)dst * 256 + 128 + c);
    m.x += a.x + b.x; m.y += a.y + b.y; m.z += a.z + b.z; m.w += a.w + b.w;
#pragma unroll
    for (int k = 0; k < EDIM; k++) {
        float av = __shfl_sync(0xffffffffu, aval, k);
        float4 w = *reinterpret_cast<const float4*>(Wes + k * 128 + c);
        m.x = fmaf(av, w.x, m.x); m.y = fmaf(av, w.y, m.y);
        m.z = fmaf(av, w.z, m.z); m.w = fmaf(av, w.w, m.w);
    }
    m.x = fmaxf(m.x, 0.f); m.y = fmaxf(m.y, 0.f);
    m.z = fmaxf(m.z, 0.f); m.w = fmaxf(m.w, 0.f);
    red_add_v4(aggr + (size_t)dst * 128 + c, m);
}

// ---------------- head: per coupling edge -----------------------------------
__global__ __launch_bounds__(256)
void head_kernel(const float* __restrict__ g12, const int* __restrict__ ei3,
                 const float* __restrict__ ea3, const float* __restrict__ ea4,
                 const float* __restrict__ Wtail, const float* __restrict__ b1,
                 const float* __restrict__ W2, const float* __restrict__ b2,
                 float* __restrict__ out)
{
    __shared__ float Ws[16 * 128];
    __shared__ float b1s[128];
    __shared__ float W2s[128];
    int tid = threadIdx.x;
    for (int i = tid; i < 16 * 128; i += 256) Ws[i] = Wtail[i];
    if (tid < 128) { b1s[tid] = b1[tid]; W2s[tid] = W2[tid]; }
    __syncthreads();
    int e    = (blockIdx.x * 256 + tid) >> 5;
    int lane = tid & 31;
    if (e >= E3N) return;
    int s = ei3[e], d = ei3[E3N + e];
    float aval = 0.f;
    if (lane < 8)       aval = ea3[(size_t)e * 8 + lane];
    else if (lane < 16) aval = ea4[(size_t)e * 8 + (lane - 8)];
    int c = lane << 2;
    float4 v = *reinterpret_cast<const float4*>(b1s + c);
    float4 a = *reinterpret_cast<const float4*>(g12 + (size_t)s * 256 + c);
    float4 b = *reinterpret_cast<const float4*>(g12 + (size_t)d * 256 + 128 + c);
    v.x += a.x + b.x; v.y += a.y + b.y; v.z += a.z + b.z; v.w += a.w + b.w;
#pragma unroll
    for (int k = 0; k < 16; k++) {
        float av = __shfl_sync(0xffffffffu, aval, k);
        float4 w = *reinterpret_cast<const float4*>(Ws + k * 128 + c);
        v.x = fmaf(av, w.x, v.x); v.y = fmaf(av, w.y, v.y);
        v.z = fmaf(av, w.z, v.z); v.w = fmaf(av, w.w, v.w);
    }
    v.x = fmaxf(v.x, 0.f); v.y = fmaxf(v.y, 0.f);
    v.z = fmaxf(v.z, 0.f); v.w = fmaxf(v.w, 0.f);
    float4 w2 = *reinterpret_cast<const float4*>(W2s + c);
    float p = v.x * w2.x + v.y * w2.y + v.z * w2.z + v.w * w2.w;
#pragma unroll
    for (int o = 16; o > 0; o >>= 1) p += __shfl_xor_sync(0xffffffffu, p, o);
    if (lane == 0) out[e] = p + b2[0];
}

// ---------------- host orchestration ----------------------------------------
extern "C" void kernel_launch(void* const* d_in, const int* in_sizes, int n_in,
                              void* d_out, int out_size)
{
    const float* x      = (const float*)d_in[0];
    const int*   ei     = (const int*)  d_in[1];
    const float* eattr  = (const float*)d_in[2];
    const int*   ei3    = (const int*)  d_in[3];
    const float* ea3    = (const float*)d_in[4];
    const float* ea4    = (const float*)d_in[5];
    const float* bn1g   = (const float*)d_in[6];
    const float* bn1b   = (const float*)d_in[7];
    const float* lin1W  = (const float*)d_in[8];
    const float* lin1b  = (const float*)d_in[9];
    const float* bn2g   = (const float*)d_in[10];
    const float* bn2b   = (const float*)d_in[11];
    const float* lin2W  = (const float*)d_in[12];
    const float* lin2b  = (const float*)d_in[13];
    const float* c1Ws   = (const float*)d_in[14];
    const float* c1Wd   = (const float*)d_in[15];
    const float* c1We   = (const float*)d_in[16];
    const float* c1bm   = (const float*)d_in[17];
    const float* c1Wu   = (const float*)d_in[18];
    const float* c1bu   = (const float*)d_in[19];
    const float* c2Ws   = (const float*)d_in[20];
    const float* c2Wd   = (const float*)d_in[21];
    const float* c2We   = (const float*)d_in[22];
    const float* c2bm   = (const float*)d_in[23];
    const float* c2Wu   = (const float*)d_in[24];
    const float* c2bu   = (const float*)d_in[25];
    const float* headW1 = (const float*)d_in[26];
    const float* headb1 = (const float*)d_in[27];
    const float* headW2 = (const float*)d_in[28];
    const float* headb2 = (const float*)d_in[29];
    float* out = (float*)d_out;

    float *h1, *hA, *hB, *hshd, *aggr, *inv1, *inv2, *st1, *st2, *W1f, *b1f, *W2f, *b2f;
    cudaGetSymbolAddress((void**)&h1,   g_h1);
    cudaGetSymbolAddress((void**)&hA,   g_hA);
    cudaGetSymbolAddress((void**)&hB,   g_hB);
    cudaGetSymbolAddress((void**)&hshd, g_hshd);
    cudaGetSymbolAddress((void**)&aggr, g_aggr);
    cudaGetSymbolAddress((void**)&inv1, g_inv1);
    cudaGetSymbolAddress((void**)&inv2, g_inv2);
    cudaGetSymbolAddress((void**)&st1,  g_stat1);
    cudaGetSymbolAddress((void**)&st2,  g_stat2);
    cudaGetSymbolAddress((void**)&W1f,  g_W1f);
    cudaGetSymbolAddress((void**)&b1f,  g_b1f);
    cudaGetSymbolAddress((void**)&W2f,  g_W2f);
    cudaGetSymbolAddress((void**)&b2f,  g_b2f);

    const int GB = (NN + 127) / 128;
    const dim3 G1(GB, 1), G2(GB, 2);

    // -------- lin_node --------
    cudaMemsetAsync(st1, 0, 32 * sizeof(float));
    stats13_kernel<<<592, 256>>>(x, st1);
    fold1_kernel<<<1, 256>>>(st1, bn1g, bn1b, lin1W, lin1b, W1f, b1f);
    cudaMemsetAsync(st2, 0, 2 * DIMF * sizeof(float));
    h1_kernel<<<(NN + H1_ROWS - 1) / H1_ROWS, 256>>>(x, W1f, b1f, h1, st2);
    cudaMemsetAsync(b2f, 0, DIM * sizeof(float));
    fold2_kernel<<<DIMF, DIM>>>(st2, bn2g, bn2b, lin2W, lin2b, W2f, b2f);
    sgemm_kernel<0, 0><<<G1, 256>>>(h1, nullptr, nullptr, W2f, nullptr, b2f, 1,
                                    hA, 128, 0, NN, 256);

    // -------- degree counts (conv1 bond graph; conv2 symmetrized) --------
    cudaMemsetAsync(inv1, 0, NN * sizeof(float));
    cudaMemsetAsync(inv2, 0, NN * sizeof(float));
    count_kernel<<<(EE + 255) / 256, 256>>>(ei + EE, EE, inv1);
    count_kernel<<<(E3N + 255) / 256, 256>>>(ei3 + E3N, E3N, inv2);
    count_kernel<<<(E3N + 255) / 256, 256>>>(ei3, E3N, inv2);
    inv_kernel<<<(NN + 255) / 256, 256>>>(inv1, NN);
    inv_kernel<<<(NN + 255) / 256, 256>>>(inv2, NN);

    float* cur = hA;
    float* nxt = hB;

    // -------- conv1 x3 --------
    for (int l = 0; l < 3; l++) {
        sgemm_kernel<0, 1><<<G2, 256>>>(cur, nullptr, nullptr,
                                        c1Ws + l * 128 * 128, c1Wd + l * 128 * 128,
                                        nullptr, 0, hshd, 256, 0, NN, 128);
        cudaMemsetAsync(aggr, 0, (size_t)NN * 128 * sizeof(float));
        edge_msg_kernel<8, false><<<EE / 8, 256>>>(hshd, ei, eattr, nullptr,
                                                   c1We + l * 8 * 128, c1bm + l * 128,
                                                   aggr, EE, 0);
        sgemm_kernel<1, 0><<<G1, 256>>>(cur, aggr, inv1, c1Wu + l * 256 * 128, nullptr,
                                        c1bu + l * 128, 1, nxt, 128, 0, NN, 256);
        float* t = cur; cur = nxt; nxt = t;
    }

    // -------- conv2 x3 (symmetrized coupling edges) --------
    for (int l = 0; l < 3; l++) {
        sgemm_kernel<0, 1><<<G2, 256>>>(cur, nullptr, nullptr,
                                        c2Ws + l * 128 * 128, c2Wd + l * 128 * 128,
                                        nullptr, 0, hshd, 256, 0, NN, 128);
        cudaMemsetAsync(aggr, 0, (size_t)NN * 128 * sizeof(float));
        edge_msg_kernel<16, true><<<(2 * E3N) / 8, 256>>>(hshd, ei3, ea3, ea4,
                                                          c2We + l * 16 * 128, c2bm + l * 128,
                                                          aggr, 2 * E3N, E3N);
        sgemm_kernel<1, 0><<<G1, 256>>>(cur, aggr, inv2, c2Wu + l * 256 * 128, nullptr,
                                        c2bu + l * 128, 1, nxt, 128, 0, NN, 256);
        float* t = cur; cur = nxt; nxt = t;
    }

    // -------- head --------
    sgemm_kernel<0, 1><<<G2, 256>>>(cur, nullptr, nullptr,
                                    headW1, headW1 + 128 * 128,
                                    nullptr, 0, hshd, 256, 0, NN, 128);
    head_kernel<<<(E3N + 7) / 8, 256>>>(hshd, ei3, ea3, ea4,
                                        headW1 + 256 * 128, headb1, headW2, headb2, out);
}

// round 3
// speedup vs baseline: 1.0220x; 1.0220x over previous
#include <cuda_runtime.h>
#include <cstdint>

#define NN      100000
#define EE      800000
#define E3N     400000
#define NODE_IN 13
#define DIM     128
#define DIMF    256

// ---------------- scratch (static __device__; no allocation allowed) -------
__device__ float g_h1  [(size_t)NN * DIMF];   // lin_node intermediate
__device__ float g_hA  [(size_t)NN * DIM];    // node features ping
__device__ float g_hB  [(size_t)NN * DIM];    // node features pong
__device__ float g_hshd[(size_t)NN * DIMF];   // [h@Wsrc | h@Wdst] per node
__device__ float g_aggr[(size_t)NN * DIM];    // scatter-mean accumulator
__device__ float g_inv1[NN];
__device__ float g_inv2[NN];
__device__ float g_stat1[32];
__device__ float g_stat2[2 * DIMF];
__device__ float g_W1f[NODE_IN * DIMF];
__device__ float g_b1f[DIMF];
__device__ float g_W2f[DIMF * DIM];
__device__ float g_b2f[DIM];

// ---------------- packed f32x2 helpers (Blackwell) --------------------------
__device__ __forceinline__ unsigned long long pack_dup_f32x2(float a)
{
    unsigned long long r;
    asm("mov.b64 %0, {%1, %1};" : "=l"(r) : "f"(a));
    return r;
}
__device__ __forceinline__ void fma_f32x2(unsigned long long& d,
                                          unsigned long long a,
                                          unsigned long long b)
{
    asm("fma.rn.f32x2 %0, %1, %2, %0;" : "+l"(d) : "l"(a), "l"(b));
}
__device__ __forceinline__ void unpack_f32x2(unsigned long long v, float& lo, float& hi)
{
    asm("mov.b64 {%0, %1}, %2;" : "=f"(lo), "=f"(hi) : "l"(v));
}

// vector global reduction: one 16B red instead of 4 scalar atomics
__device__ __forceinline__ void red_add_v4(float* p, float4 v)
{
#if __CUDA_ARCH__ >= 900
    asm volatile("red.global.add.v4.f32 [%0], {%1, %2, %3, %4};"
                 :: "l"(p), "f"(v.x), "f"(v.y), "f"(v.z), "f"(v.w) : "memory");
#else
    atomicAdd(p + 0, v.x); atomicAdd(p + 1, v.y);
    atomicAdd(p + 2, v.z); atomicAdd(p + 3, v.w);
#endif
}

// ---------------- column stats of x (13 cols) ------------------------------
__global__ void stats13_kernel(const float* __restrict__ x, float* __restrict__ stat)
{
    float ls[NODE_IN], lq[NODE_IN];
#pragma unroll
    for (int c = 0; c < NODE_IN; c++) { ls[c] = 0.f; lq[c] = 0.f; }
    int stride = gridDim.x * blockDim.x;
    for (int r = blockIdx.x * blockDim.x + threadIdx.x; r < NN; r += stride) {
#pragma unroll
        for (int c = 0; c < NODE_IN; c++) {
            float v = x[(size_t)r * NODE_IN + c];
            ls[c] += v; lq[c] += v * v;
        }
    }
    __shared__ float ss[2 * NODE_IN];
    if (threadIdx.x < 2 * NODE_IN) ss[threadIdx.x] = 0.f;
    __syncthreads();
#pragma unroll
    for (int c = 0; c < NODE_IN; c++) {
        atomicAdd(&ss[c], ls[c]);
        atomicAdd(&ss[NODE_IN + c], lq[c]);
    }
    __syncthreads();
    if (threadIdx.x < 2 * NODE_IN) atomicAdd(&stat[threadIdx.x], ss[threadIdx.x]);
}

// ---------------- fold bn1 into lin1 ---------------------------------------
__global__ void fold1_kernel(const float* __restrict__ stat,
                             const float* __restrict__ g, const float* __restrict__ b,
                             const float* __restrict__ W1, const float* __restrict__ b1,
                             float* __restrict__ W1f, float* __restrict__ b1f)
{
    __shared__ float alpha[NODE_IN], beta[NODE_IN];
    int t = threadIdx.x;  // 0..255 = output column
    if (t < NODE_IN) {
        float m = stat[t] * (1.0f / NN);
        float v = stat[NODE_IN + t] * (1.0f / NN) - m * m;
        float a = g[t] * rsqrtf(v + 1e-5f);
        alpha[t] = a;
        beta[t]  = b[t] - m * a;
    }
    __syncthreads();
    float acc = b1[t];
#pragma unroll
    for (int k = 0; k < NODE_IN; k++) {
        float w = W1[k * DIMF + t];
        W1f[k * DIMF + t] = alpha[k] * w;
        acc += beta[k] * w;
    }
    b1f[t] = acc;
}

// ---------------- h1 = relu(x @ W1f + b1f) + column stats of h1 -------------
#define H1_ROWS 64
__global__ __launch_bounds__(256)
void h1_kernel(const float* __restrict__ x, const float* __restrict__ W1f,
               const float* __restrict__ b1f, float* __restrict__ h1,
               float* __restrict__ stat2)
{
    __shared__ float xs[H1_ROWS * NODE_IN];
    int t  = threadIdx.x;            // output column 0..255
    int r0 = blockIdx.x * H1_ROWS;
    int nr = min(H1_ROWS, NN - r0);
    for (int i = t; i < nr * NODE_IN; i += 256)
        xs[i] = x[(size_t)r0 * NODE_IN + i];
    __syncthreads();
    float w[NODE_IN];
#pragma unroll
    for (int k = 0; k < NODE_IN; k++) w[k] = W1f[k * DIMF + t];
    float bb = b1f[t];
    float s = 0.f, q = 0.f;
    for (int r = 0; r < nr; r++) {
        float acc = bb;
#pragma unroll
        for (int k = 0; k < NODE_IN; k++) acc = fmaf(xs[r * NODE_IN + k], w[k], acc);
        acc = fmaxf(acc, 0.f);
        h1[(size_t)(r0 + r) * DIMF + t] = acc;
        s += acc; q += acc * acc;
    }
    atomicAdd(&stat2[t], s);
    atomicAdd(&stat2[DIMF + t], q);
}

// ---------------- fold bn2 into lin2 ---------------------------------------
__global__ void fold2_kernel(const float* __restrict__ stat2,
                             const float* __restrict__ g, const float* __restrict__ b,
                             const float* __restrict__ W2, const float* __restrict__ b2,
                             float* __restrict__ W2f, float* __restrict__ b2f)
{
    int k = blockIdx.x;   // 0..255 input channel
    int j = threadIdx.x;  // 0..127 output channel
    __shared__ float al, be;
    if (j == 0) {
        float m = stat2[k] * (1.0f / NN);
        float v = stat2[DIMF + k] * (1.0f / NN) - m * m;
        float a = g[k] * rsqrtf(v + 1e-5f);
        al = a; be = b[k] - m * a;
    }
    __syncthreads();
    float w = W2[k * DIM + j];
    W2f[k * DIM + j] = al * w;
    float contrib = be * w;
    if (k == 0) contrib += b2[j];
    atomicAdd(&b2f[j], contrib);
}

// ---------------- degree counting -------------------------------------------
__global__ void count_kernel(const int* __restrict__ dst, int n, float* __restrict__ cnt)
{
    int i = blockIdx.x * blockDim.x + threadIdx.x;
    if (i < n) atomicAdd(&cnt[dst[i]], 1.0f);
}
__global__ void inv_kernel(float* __restrict__ c, int n)
{
    int i = blockIdx.x * blockDim.x + threadIdx.x;
    if (i < n) c[i] = 1.0f / fmaxf(c[i], 1.0f);
}

// ---------------- tall-skinny SGEMM: C = [relu](A @ B + bias) ---------------
// A: Nrows x K row-major (MODEA=0) or concat [A | A2*scale2] with K=256 (MODEA=1)
// B: K x 128 row-major. C row ldc, column offset colOff.
// DUAL=1: blockIdx.y selects (B0, colOff 0) vs (B1, colOff 128); K=128.
// Mainloop uses packed fma.rn.f32x2 (2 fp32 FMA per issue slot).
template<int MODEA, int DUAL>
__global__ __launch_bounds__(256, 2)
void sgemm_kernel(const float* __restrict__ A, const float* __restrict__ A2,
                  const float* __restrict__ scale2,
                  const float* __restrict__ B0, const float* __restrict__ B1,
                  const float* __restrict__ bias, int relu,
                  float* __restrict__ C, int ldc, int colOff,
                  int Nrows, int K)
{
    const float* B = B0;
    if (DUAL && blockIdx.y == 1) { B = B1; colOff += 128; }
    __shared__ float As[16][129];
    __shared__ float Bs[16][128];
    int tid  = threadIdx.x;
    int tx   = tid & 15, ty = tid >> 4;
    int brow = blockIdx.x * 128;
    unsigned long long acc2[8][4];   // rows i=0..7; col pairs j2=0..3 (cols 2j2,2j2+1)
#pragma unroll
    for (int i = 0; i < 8; i++)
#pragma unroll
        for (int j = 0; j < 4; j++) acc2[i][j] = 0ull;

    for (int k0 = 0; k0 < K; k0 += 16) {
        __syncthreads();
#pragma unroll
        for (int i = 0; i < 2; i++) {
            int lin = tid + i * 256;
            int r   = lin >> 2;
            int kq  = (lin & 3) << 2;
            int grow = brow + r;
            float4 v = make_float4(0.f, 0.f, 0.f, 0.f);
            if (grow < Nrows) {
                int kk = k0 + kq;
                if (MODEA == 0) {
                    v = *reinterpret_cast<const float4*>(A + (size_t)grow * K + kk);
                } else {
                    if (kk < 128) {
                        v = *reinterpret_cast<const float4*>(A + (size_t)grow * 128 + kk);
                    } else {
                        v = *reinterpret_cast<const float4*>(A2 + (size_t)grow * 128 + (kk - 128));
                        float s = scale2[grow];
                        v.x *= s; v.y *= s; v.z *= s; v.w *= s;
                    }
                }
            }
            As[kq + 0][r] = v.x; As[kq + 1][r] = v.y;
            As[kq + 2][r] = v.z; As[kq + 3][r] = v.w;
        }
#pragma unroll
        for (int i = 0; i < 2; i++) {
            int lin = tid + i * 256;
            int kk  = lin >> 5;
            int c4  = (lin & 31) << 2;
            *reinterpret_cast<float4*>(&Bs[kk][c4]) =
                *reinterpret_cast<const float4*>(B + (size_t)(k0 + kk) * 128 + c4);
        }
        __syncthreads();
#pragma unroll
        for (int kk = 0; kk < 16; kk++) {
            unsigned long long av[8], bv[4];
#pragma unroll
            for (int i = 0; i < 8; i++)
                av[i] = pack_dup_f32x2(As[kk][ty * 8 + i]);
#pragma unroll
            for (int j = 0; j < 4; j++)
                bv[j] = *reinterpret_cast<const unsigned long long*>(&Bs[kk][tx * 8 + 2 * j]);
#pragma unroll
            for (int i = 0; i < 8; i++)
#pragma unroll
                for (int j = 0; j < 4; j++)
                    fma_f32x2(acc2[i][j], av[i], bv[j]);
        }
    }
#pragma unroll
    for (int i = 0; i < 8; i++) {
        int grow = brow + ty * 8 + i;
        if (grow >= Nrows) continue;
#pragma unroll
        for (int jh = 0; jh < 2; jh++) {
            int col = tx * 8 + jh * 4;
            float4 o;
            unpack_f32x2(acc2[i][jh * 2 + 0], o.x, o.y);
            unpack_f32x2(acc2[i][jh * 2 + 1], o.z, o.w);
            if (bias) {
                float4 bb = *reinterpret_cast<const float4*>(bias + col);
                o.x += bb.x; o.y += bb.y; o.z += bb.z; o.w += bb.w;
            }
            if (relu) {
                o.x = fmaxf(o.x, 0.f); o.y = fmaxf(o.y, 0.f);
                o.z = fmaxf(o.z, 0.f); o.w = fmaxf(o.w, 0.f);
            }
            *reinterpret_cast<float4*>(C + (size_t)grow * ldc + colOff + col) = o;
        }
    }
}

// ---------------- edge message + scatter-add --------------------------------
// msg = relu(hs[src] + hd[dst] + ea@We + bm); aggr[dst] += msg (vector red)
template<int EDIM, bool SYM>
__global__ __launch_bounds__(256)
void edge_msg_kernel(const float* __restrict__ hshd,
                     const int* __restrict__ ei,
                     const float* __restrict__ ea, const float* __restrict__ eb,
                     const float* __restrict__ We, const float* __restrict__ bm,
                     float* __restrict__ aggr, int Etot, int Ehalf)
{
    __shared__ float Wes[EDIM * 128];
    __shared__ float bms[128];
    int tid = threadIdx.x;
    for (int i = tid; i < EDIM * 128; i += 256) Wes[i] = We[i];
    if (tid < 128) bms[tid] = bm[tid];
    __syncthreads();
    int e    = (blockIdx.x * 256 + tid) >> 5;
    int lane = tid & 31;
    if (e >= Etot) return;
    int src, dst, eidx;
    if (SYM) {
        src = ei[e];
        if (e < Ehalf) { dst = ei[e + Ehalf]; eidx = e; }
        else           { dst = ei[e - Ehalf]; eidx = e - Ehalf; }
    } else {
        src = ei[e]; dst = ei[Etot + e]; eidx = e;
    }
    float aval = 0.f;
    if (SYM) {
        if (lane < 8)       aval = ea[(size_t)eidx * 8 + lane];
        else if (lane < 16) aval = eb[(size_t)eidx * 8 + (lane - 8)];
    } else {
        if (lane < EDIM)    aval = ea[(size_t)eidx * EDIM + lane];
    }
    int c = lane << 2;
    float4 m = *reinterpret_cast<const float4*>(bms + c);
    float4 a = *reinterpret_cast<const float4*>(hshd + (size_t)src * 256 + c);
    float4 b = *reinterpret_cast<const float4*>(hshd + (size_t)dst * 256 + 128 + c);
    m.x += a.x + b.x; m.y += a.y + b.y; m.z += a.z + b.z; m.w += a.w + b.w;
#pragma unroll
    for (int k = 0; k < EDIM; k++) {
        float av = __shfl_sync(0xffffffffu, aval, k);
        float4 w = *reinterpret_cast<const float4*>(Wes + k * 128 + c);
        m.x = fmaf(av, w.x, m.x); m.y = fmaf(av, w.y, m.y);
        m.z = fmaf(av, w.z, m.z); m.w = fmaf(av, w.w, m.w);
    }
    m.x = fmaxf(m.x, 0.f); m.y = fmaxf(m.y, 0.f);
    m.z = fmaxf(m.z, 0.f); m.w = fmaxf(m.w, 0.f);
    red_add_v4(aggr + (size_t)dst * 128 + c, m);
}

// ---------------- head: per coupling edge -----------------------------------
__global__ __launch_bounds__(256)
void head_kernel(const float* __restrict__ g12, const int* __restrict__ ei3,
                 const float* __restrict__ ea3, const float* __restrict__ ea4,
                 const float* __restrict__ Wtail, const float* __restrict__ b1,
                 const float* __restrict__ W2, const float* __restrict__ b2,
                 float* __restrict__ out)
{
    __shared__ float Ws[16 * 128];
    __shared__ float b1s[128];
    __shared__ float W2s[128];
    int tid = threadIdx.x;
    for (int i = tid; i < 16 * 128; i += 256) Ws[i] = Wtail[i];
    if (tid < 128) { b1s[tid] = b1[tid]; W2s[tid] = W2[tid]; }
    __syncthreads();
    int e    = (blockIdx.x * 256 + tid) >> 5;
    int lane = tid & 31;
    if (e >= E3N) return;
    int s = ei3[e], d = ei3[E3N + e];
    float aval = 0.f;
    if (lane < 8)       aval = ea3[(size_t)e * 8 + lane];
    else if (lane < 16) aval = ea4[(size_t)e * 8 + (lane - 8)];
    int c = lane << 2;
    float4 v = *reinterpret_cast<const float4*>(b1s + c);
    float4 a = *reinterpret_cast<const float4*>(g12 + (size_t)s * 256 + c);
    float4 b = *reinterpret_cast<const float4*>(g12 + (size_t)d * 256 + 128 + c);
    v.x += a.x + b.x; v.y += a.y + b.y; v.z += a.z + b.z; v.w += a.w + b.w;
#pragma unroll
    for (int k = 0; k < 16; k++) {
        float av = __shfl_sync(0xffffffffu, aval, k);
        float4 w = *reinterpret_cast<const float4*>(Ws + k * 128 + c);
        v.x = fmaf(av, w.x, v.x); v.y = fmaf(av, w.y, v.y);
        v.z = fmaf(av, w.z, v.z); v.w = fmaf(av, w.w, v.w);
    }
    v.x = fmaxf(v.x, 0.f); v.y = fmaxf(v.y, 0.f);
    v.z = fmaxf(v.z, 0.f); v.w = fmaxf(v.w, 0.f);
    float4 w2 = *reinterpret_cast<const float4*>(W2s + c);
    float p = v.x * w2.x + v.y * w2.y + v.z * w2.z + v.w * w2.w;
#pragma unroll
    for (int o = 16; o > 0; o >>= 1) p += __shfl_xor_sync(0xffffffffu, p, o);
    if (lane == 0) out[e] = p + b2[0];
}

// ---------------- host orchestration ----------------------------------------
extern "C" void kernel_launch(void* const* d_in, const int* in_sizes, int n_in,
                              void* d_out, int out_size)
{
    const float* x      = (const float*)d_in[0];
    const int*   ei     = (const int*)  d_in[1];
    const float* eattr  = (const float*)d_in[2];
    const int*   ei3    = (const int*)  d_in[3];
    const float* ea3    = (const float*)d_in[4];
    const float* ea4    = (const float*)d_in[5];
    const float* bn1g   = (const float*)d_in[6];
    const float* bn1b   = (const float*)d_in[7];
    const float* lin1W  = (const float*)d_in[8];
    const float* lin1b  = (const float*)d_in[9];
    const float* bn2g   = (const float*)d_in[10];
    const float* bn2b   = (const float*)d_in[11];
    const float* lin2W  = (const float*)d_in[12];
    const float* lin2b  = (const float*)d_in[13];
    const float* c1Ws   = (const float*)d_in[14];
    const float* c1Wd   = (const float*)d_in[15];
    const float* c1We   = (const float*)d_in[16];
    const float* c1bm   = (const float*)d_in[17];
    const float* c1Wu   = (const float*)d_in[18];
    const float* c1bu   = (const float*)d_in[19];
    const float* c2Ws   = (const float*)d_in[20];
    const float* c2Wd   = (const float*)d_in[21];
    const float* c2We   = (const float*)d_in[22];
    const float* c2bm   = (const float*)d_in[23];
    const float* c2Wu   = (const float*)d_in[24];
    const float* c2bu   = (const float*)d_in[25];
    const float* headW1 = (const float*)d_in[26];
    const float* headb1 = (const float*)d_in[27];
    const float* headW2 = (const float*)d_in[28];
    const float* headb2 = (const float*)d_in[29];
    float* out = (float*)d_out;

    float *h1, *hA, *hB, *hshd, *aggr, *inv1, *inv2, *st1, *st2, *W1f, *b1f, *W2f, *b2f;
    cudaGetSymbolAddress((void**)&h1,   g_h1);
    cudaGetSymbolAddress((void**)&hA,   g_hA);
    cudaGetSymbolAddress((void**)&hB,   g_hB);
    cudaGetSymbolAddress((void**)&hshd, g_hshd);
    cudaGetSymbolAddress((void**)&aggr, g_aggr);
    cudaGetSymbolAddress((void**)&inv1, g_inv1);
    cudaGetSymbolAddress((void**)&inv2, g_inv2);
    cudaGetSymbolAddress((void**)&st1,  g_stat1);
    cudaGetSymbolAddress((void**)&st2,  g_stat2);
    cudaGetSymbolAddress((void**)&W1f,  g_W1f);
    cudaGetSymbolAddress((void**)&b1f,  g_b1f);
    cudaGetSymbolAddress((void**)&W2f,  g_W2f);
    cudaGetSymbolAddress((void**)&b2f,  g_b2f);

    const int GB = (NN + 127) / 128;
    const dim3 G1(GB, 1), G2(GB, 2);

    // -------- lin_node --------
    cudaMemsetAsync(st1, 0, 32 * sizeof(float));
    stats13_kernel<<<592, 256>>>(x, st1);
    fold1_kernel<<<1, 256>>>(st1, bn1g, bn1b, lin1W, lin1b, W1f, b1f);
    cudaMemsetAsync(st2, 0, 2 * DIMF * sizeof(float));
    h1_kernel<<<(NN + H1_ROWS - 1) / H1_ROWS, 256>>>(x, W1f, b1f, h1, st2);
    cudaMemsetAsync(b2f, 0, DIM * sizeof(float));
    fold2_kernel<<<DIMF, DIM>>>(st2, bn2g, bn2b, lin2W, lin2b, W2f, b2f);
    sgemm_kernel<0, 0><<<G1, 256>>>(h1, nullptr, nullptr, W2f, nullptr, b2f, 1,
                                    hA, 128, 0, NN, 256);

    // -------- degree counts (conv1 bond graph; conv2 symmetrized) --------
    cudaMemsetAsync(inv1, 0, NN * sizeof(float));
    cudaMemsetAsync(inv2, 0, NN * sizeof(float));
    count_kernel<<<(EE + 255) / 256, 256>>>(ei + EE, EE, inv1);
    count_kernel<<<(E3N + 255) / 256, 256>>>(ei3 + E3N, E3N, inv2);
    count_kernel<<<(E3N + 255) / 256, 256>>>(ei3, E3N, inv2);
    inv_kernel<<<(NN + 255) / 256, 256>>>(inv1, NN);
    inv_kernel<<<(NN + 255) / 256, 256>>>(inv2, NN);

    float* cur = hA;
    float* nxt = hB;

    // -------- conv1 x3 --------
    for (int l = 0; l < 3; l++) {
        sgemm_kernel<0, 1><<<G2, 256>>>(cur, nullptr, nullptr,
                                        c1Ws + l * 128 * 128, c1Wd + l * 128 * 128,
                                        nullptr, 0, hshd, 256, 0, NN, 128);
        cudaMemsetAsync(aggr, 0, (size_t)NN * 128 * sizeof(float));
        edge_msg_kernel<8, false><<<EE / 8, 256>>>(hshd, ei, eattr, nullptr,
                                                   c1We + l * 8 * 128, c1bm + l * 128,
                                                   aggr, EE, 0);
        sgemm_kernel<1, 0><<<G1, 256>>>(cur, aggr, inv1, c1Wu + l * 256 * 128, nullptr,
                                        c1bu + l * 128, 1, nxt, 128, 0, NN, 256);
        float* t = cur; cur = nxt; nxt = t;
    }

    // -------- conv2 x3 (symmetrized coupling edges) --------
    for (int l = 0; l < 3; l++) {
        sgemm_kernel<0, 1><<<G2, 256>>>(cur, nullptr, nullptr,
                                        c2Ws + l * 128 * 128, c2Wd + l * 128 * 128,
                                        nullptr, 0, hshd, 256, 0, NN, 128);
        cudaMemsetAsync(aggr, 0, (size_t)NN * 128 * sizeof(float));
        edge_msg_kernel<16, true><<<(2 * E3N) / 8, 256>>>(hshd, ei3, ea3, ea4,
                                                          c2We + l * 16 * 128, c2bm + l * 128,
                                                          aggr, 2 * E3N, E3N);
        sgemm_kernel<1, 0><<<G1, 256>>>(cur, aggr, inv2, c2Wu + l * 256 * 128, nullptr,
                                        c2bu + l * 128, 1, nxt, 128, 0, NN, 256);
        float* t = cur; cur = nxt; nxt = t;
    }

    // -------- head --------
    sgemm_kernel<0, 1><<<G2, 256>>>(cur, nullptr, nullptr,
                                    headW1, headW1 + 128 * 128,
                                    nullptr, 0, hshd, 256, 0, NN, 128);
    head_kernel<<<(E3N + 7) / 8, 256>>>(hshd, ei3, ea3, ea4,
                                        headW1 + 256 * 128, headb1, headW2, headb2, out);
}

// round 5
// speedup vs baseline: 1.1668x; 1.1417x over previous
#include <cuda_runtime.h>
#include <cstdint>

#define NN      100000
#define EE      800000
#define E3N     400000
#define NODE_IN 13
#define DIM     128
#define DIMF    256

// ---------------- scratch (static __device__; no allocation allowed) -------
__device__ float g_h1  [(size_t)NN * DIMF];   // lin_node intermediate
__device__ float g_hA  [(size_t)NN * DIM];    // node features ping
__device__ float g_hB  [(size_t)NN * DIM];    // node features pong
__device__ float g_hshd[(size_t)NN * DIMF];   // [h@Wsrc | h@Wdst] per node
__device__ float g_aggr[(size_t)NN * DIM];    // scatter-mean accumulator
__device__ float g_inv1[NN];
__device__ float g_inv2[NN];
__device__ float g_stat1[32];
__device__ float g_stat2[2 * DIMF];
__device__ float g_W2f[DIMF * DIM];
__device__ float g_b2f[DIM];

// ---------------- packed f32x2 helpers (Blackwell) --------------------------
__device__ __forceinline__ unsigned long long pack_dup_f32x2(float a)
{
    unsigned long long r;
    asm("mov.b64 %0, {%1, %1};" : "=l"(r) : "f"(a));
    return r;
}
__device__ __forceinline__ void fma_f32x2(unsigned long long& d,
                                          unsigned long long a,
                                          unsigned long long b)
{
    asm("fma.rn.f32x2 %0, %1, %2, %0;" : "+l"(d) : "l"(a), "l"(b));
}
__device__ __forceinline__ void unpack_f32x2(unsigned long long v, float& lo, float& hi)
{
    asm("mov.b64 {%0, %1}, %2;" : "=f"(lo), "=f"(hi) : "l"(v));
}

// ---------------- cp.async helpers ------------------------------------------
__device__ __forceinline__ unsigned smem_u32(const void* p)
{
    return (unsigned)__cvta_generic_to_shared(p);
}
__device__ __forceinline__ void cp_async16(unsigned sa, const void* g)
{
    asm volatile("cp.async.cg.shared.global [%0], [%1], 16;"
                 :: "r"(sa), "l"(g) : "memory");
}
#define CP_COMMIT() asm volatile("cp.async.commit_group;" ::: "memory")
#define CP_WAIT1()  asm volatile("cp.async.wait_group 1;" ::: "memory")
#define CP_WAIT0()  asm volatile("cp.async.wait_group 0;" ::: "memory")

// vector global reduction: one 16B red instead of 4 scalar atomics
__device__ __forceinline__ void red_add_v4(float* p, float4 v)
{
    asm volatile("red.global.add.v4.f32 [%0], {%1, %2, %3, %4};"
                 :: "l"(p), "f"(v.x), "f"(v.y), "f"(v.z), "f"(v.w) : "memory");
}

// ---------------- column stats of x (13 cols) ------------------------------
__global__ void stats13_kernel(const float* __restrict__ x, float* __restrict__ stat)
{
    float ls[NODE_IN], lq[NODE_IN];
#pragma unroll
    for (int c = 0; c < NODE_IN; c++) { ls[c] = 0.f; lq[c] = 0.f; }
    int stride = gridDim.x * blockDim.x;
    for (int r = blockIdx.x * blockDim.x + threadIdx.x; r < NN; r += stride) {
#pragma unroll
        for (int c = 0; c < NODE_IN; c++) {
            float v = x[(size_t)r * NODE_IN + c];
            ls[c] += v; lq[c] += v * v;
        }
    }
    __shared__ float ss[2 * NODE_IN];
    if (threadIdx.x < 2 * NODE_IN) ss[threadIdx.x] = 0.f;
    __syncthreads();
#pragma unroll
    for (int c = 0; c < NODE_IN; c++) {
        atomicAdd(&ss[c], ls[c]);
        atomicAdd(&ss[NODE_IN + c], lq[c]);
    }
    __syncthreads();
    if (threadIdx.x < 2 * NODE_IN) atomicAdd(&stat[threadIdx.x], ss[threadIdx.x]);
}

// ------- h1 = relu(bn1(x) @ W1 + b1) with bn fold computed inline -----------
#define H1_ROWS 64
__global__ __launch_bounds__(256)
void h1_kernel(const float* __restrict__ x, const float* __restrict__ stat,
               const float* __restrict__ bn1g, const float* __restrict__ bn1b,
               const float* __restrict__ W1, const float* __restrict__ b1,
               float* __restrict__ h1, float* __restrict__ stat2)
{
    __shared__ float xs[H1_ROWS * NODE_IN];
    int t  = threadIdx.x;            // output column 0..255
    // fold bn1 into per-thread weights
    float w[NODE_IN];
    float bb = b1[t];
#pragma unroll
    for (int k = 0; k < NODE_IN; k++) {
        float m = stat[k] * (1.0f / NN);
        float v = stat[NODE_IN + k] * (1.0f / NN) - m * m;
        float a = bn1g[k] * rsqrtf(v + 1e-5f);
        float be = bn1b[k] - m * a;
        float wv = W1[k * DIMF + t];
        w[k] = a * wv;
        bb += be * wv;
    }
    int r0 = blockIdx.x * H1_ROWS;
    int nr = min(H1_ROWS, NN - r0);
    for (int i = t; i < nr * NODE_IN; i += 256)
        xs[i] = x[(size_t)r0 * NODE_IN + i];
    __syncthreads();
    float s = 0.f, q = 0.f;
    for (int r = 0; r < nr; r++) {
        float acc = bb;
#pragma unroll
        for (int k = 0; k < NODE_IN; k++) acc = fmaf(xs[r * NODE_IN + k], w[k], acc);
        acc = fmaxf(acc, 0.f);
        h1[(size_t)(r0 + r) * DIMF + t] = acc;
        s += acc; q += acc * acc;
    }
    atomicAdd(&stat2[t], s);
    atomicAdd(&stat2[DIMF + t], q);
}

// ---------------- fold bn2 into lin2 (atomic-free) ---------------------------
__global__ void fold2_kernel(const float* __restrict__ stat2,
                             const float* __restrict__ g, const float* __restrict__ b,
                             const float* __restrict__ W2, const float* __restrict__ b2,
                             float* __restrict__ W2f, float* __restrict__ b2f)
{
    int k = blockIdx.x;   // 0..255 input channel
    int j = threadIdx.x;  // 0..127 output channel
    __shared__ float al;
    if (j == 0) {
        float m = stat2[k] * (1.0f / NN);
        float v = stat2[DIMF + k] * (1.0f / NN) - m * m;
        al = g[k] * rsqrtf(v + 1e-5f);
    }
    __syncthreads();
    W2f[k * DIM + j] = al * W2[k * DIM + j];
    if (k == 0) {
        float acc = b2[j];
        for (int kk = 0; kk < DIMF; kk++) {
            float m = stat2[kk] * (1.0f / NN);
            float v = stat2[DIMF + kk] * (1.0f / NN) - m * m;
            float a = g[kk] * rsqrtf(v + 1e-5f);
            float be = b[kk] - m * a;
            acc += be * W2[kk * DIM + j];
        }
        b2f[j] = acc;
    }
}

// ---------------- degree counting -------------------------------------------
__global__ void count_kernel(const int* __restrict__ dst, int n, float* __restrict__ cnt)
{
    int i = blockIdx.x * blockDim.x + threadIdx.x;
    if (i < n) atomicAdd(&cnt[dst[i]], 1.0f);
}
__global__ void inv_kernel(float* __restrict__ c, int n)
{
    int i = blockIdx.x * blockDim.x + threadIdx.x;
    if (i < n) c[i] = 1.0f / fmaxf(c[i], 1.0f);
}

// ---------------- pipelined tall-skinny SGEMM -------------------------------
// C[:, colOff:colOff+128] = [relu](A @ B + bias)
// MODEA=0: A is Nrows x K. MODEA=1: A = [A | A2 * scale2] (K=256).
// DUAL=1: blockIdx.y picks (B0, col 0) / (B1, col 128); K=128.
// B tiles double-buffered via cp.async; A tiles prefetched via LDG+deferred STS.
// Thread (tx,ty) computes rows ty*8..+7, cols {tx*4..+3, 64+tx*4..+3}.
template<int MODEA, int DUAL>
__global__ __launch_bounds__(256, 2)
void sgemm_kernel(const float* __restrict__ A, const float* __restrict__ A2,
                  const float* __restrict__ scale2,
                  const float* __restrict__ B0, const float* __restrict__ B1,
                  const float* __restrict__ bias, int relu,
                  float* __restrict__ C, int ldc, int colOff,
                  int Nrows, int K)
{
    const float* Bm = B0;
    if (DUAL && blockIdx.y == 1) { Bm = B1; colOff += 128; }
    __shared__ float As[2][16][133];   // k-major, padded: conflict-free reads/writes
    __shared__ float Bs[2][16][132];   // row pad 132 (528B, 16B-aligned for cp.async)
    int tid  = threadIdx.x;
    int tx   = tid & 15, ty = tid >> 4;
    int brow = blockIdx.x * 128;
    const int T = K / 16;

    // A granule mapping (two 16B granules per thread)
    int r0g = tid >> 2,          kq0 = (tid & 3) << 2;
    int r1g = (tid + 256) >> 2,  kq1 = ((tid + 256) & 3) << 2;
    float s0 = 1.f, s1 = 1.f;
    if (MODEA == 1) {
        s0 = (brow + r0g < Nrows) ? scale2[brow + r0g] : 0.f;
        s1 = (brow + r1g < Nrows) ? scale2[brow + r1g] : 0.f;
    }

    float4 stg0, stg1;
    auto ldgA = [&](int t) {
        int k0 = t * 16;
        {
            int grow = brow + r0g; int kk = k0 + kq0;
            float4 v = make_float4(0.f, 0.f, 0.f, 0.f);
            if (grow < Nrows) {
                const float* p;
                if (MODEA == 1)
                    p = (kk < 128) ? A + (size_t)grow * 128 + kk
                                   : A2 + (size_t)grow * 128 + (kk - 128);
                else
                    p = A + (size_t)grow * K + kk;
                v = *reinterpret_cast<const float4*>(p);
                if (MODEA == 1 && kk >= 128) { v.x *= s0; v.y *= s0; v.z *= s0; v.w *= s0; }
            }
            stg0 = v;
        }
        {
            int grow = brow + r1g; int kk = k0 + kq1;
            float4 v = make_float4(0.f, 0.f, 0.f, 0.f);
            if (grow < Nrows) {
                const float* p;
                if (MODEA == 1)
                    p = (kk < 128) ? A + (size_t)grow * 128 + kk
                                   : A2 + (size_t)grow * 128 + (kk - 128);
                else
                    p = A + (size_t)grow * K + kk;
                v = *reinterpret_cast<const float4*>(p);
                if (MODEA == 1 && kk >= 128) { v.x *= s1; v.y *= s1; v.z *= s1; v.w *= s1; }
            }
            stg1 = v;
        }
    };
    auto stsA = [&](int buf) {
        As[buf][kq0 + 0][r0g] = stg0.x; As[buf][kq0 + 1][r0g] = stg0.y;
        As[buf][kq0 + 2][r0g] = stg0.z; As[buf][kq0 + 3][r0g] = stg0.w;
        As[buf][kq1 + 0][r1g] = stg1.x; As[buf][kq1 + 1][r1g] = stg1.y;
        As[buf][kq1 + 2][r1g] = stg1.z; As[buf][kq1 + 3][r1g] = stg1.w;
    };
    auto ldB = [&](int t, int buf) {
        int k0 = t * 16;
        int kka = tid >> 5,        c4a = (tid & 31) << 2;
        int kkb = (tid + 256) >> 5, c4b = ((tid + 256) & 31) << 2;
        cp_async16(smem_u32(&Bs[buf][kka][c4a]), Bm + (size_t)(k0 + kka) * 128 + c4a);
        cp_async16(smem_u32(&Bs[buf][kkb][c4b]), Bm + (size_t)(k0 + kkb) * 128 + c4b);
        CP_COMMIT();
    };

    unsigned long long acc2[8][4];
#pragma unroll
    for (int i = 0; i < 8; i++)
#pragma unroll
        for (int j = 0; j < 4; j++) acc2[i][j] = 0ull;

    ldgA(0); stsA(0); ldB(0, 0);
    for (int t = 0; t < T; t++) {
        int buf = t & 1;
        if (t + 1 < T) { ldgA(t + 1); ldB(t + 1, buf ^ 1); CP_WAIT1(); }
        else           { CP_WAIT0(); }
        __syncthreads();
#pragma unroll
        for (int kk = 0; kk < 16; kk++) {
            unsigned long long av[8], bv[4];
#pragma unroll
            for (int i = 0; i < 8; i++)
                av[i] = pack_dup_f32x2(As[buf][kk][ty * 8 + i]);
            {
                ulonglong2 p0 = *reinterpret_cast<const ulonglong2*>(&Bs[buf][kk][tx * 4]);
                ulonglong2 p1 = *reinterpret_cast<const ulonglong2*>(&Bs[buf][kk][64 + tx * 4]);
                bv[0] = p0.x; bv[1] = p0.y; bv[2] = p1.x; bv[3] = p1.y;
            }
#pragma unroll
            for (int i = 0; i < 8; i++)
#pragma unroll
                for (int j = 0; j < 4; j++)
                    fma_f32x2(acc2[i][j], av[i], bv[j]);
        }
        __syncthreads();
        if (t + 1 < T) stsA(buf ^ 1);
    }

#pragma unroll
    for (int i = 0; i < 8; i++) {
        int grow = brow + ty * 8 + i;
        if (grow >= Nrows) continue;
#pragma unroll
        for (int h = 0; h < 2; h++) {
            int col = h * 64 + tx * 4;
            float4 o;
            unpack_f32x2(acc2[i][h * 2 + 0], o.x, o.y);
            unpack_f32x2(acc2[i][h * 2 + 1], o.z, o.w);
            if (bias) {
                float4 bb = *reinterpret_cast<const float4*>(bias + col);
                o.x += bb.x; o.y += bb.y; o.z += bb.z; o.w += bb.w;
            }
            if (relu) {
                o.x = fmaxf(o.x, 0.f); o.y = fmaxf(o.y, 0.f);
                o.z = fmaxf(o.z, 0.f); o.w = fmaxf(o.w, 0.f);
            }
            *reinterpret_cast<float4*>(C + (size_t)grow * ldc + colOff + col) = o;
        }
    }
}

// ---------------- edge message + scatter-add (grid-stride) ------------------
// msg = relu(hs[src] + hd[dst] + ea@We + bm); aggr[dst] += msg (vector red)
template<int EDIM, bool SYM>
__global__ __launch_bounds__(256)
void edge_msg_kernel(const float* __restrict__ hshd,
                     const int* __restrict__ ei,
                     const float* __restrict__ ea, const float* __restrict__ eb,
                     const float* __restrict__ We, const float* __restrict__ bm,
                     float* __restrict__ aggr, int Etot, int Ehalf)
{
    __shared__ float Wes[EDIM * 128];
    __shared__ float bms[128];
    int tid = threadIdx.x;
    for (int i = tid; i < EDIM * 128; i += 256) Wes[i] = We[i];
    if (tid < 128) bms[tid] = bm[tid];
    __syncthreads();
    int wglob = blockIdx.x * 8 + (tid >> 5);
    int lane  = tid & 31;
    int step  = gridDim.x * 8;
    int c = lane << 2;
    for (int e = wglob; e < Etot; e += step) {
        int src, dst, eidx;
        if (SYM) {
            src = ei[e];
            if (e < Ehalf) { dst = ei[e + Ehalf]; eidx = e; }
            else           { dst = ei[e - Ehalf]; eidx = e - Ehalf; }
        } else {
            src = ei[e]; dst = ei[Etot + e]; eidx = e;
        }
        float aval = 0.f;
        if (SYM) {
            if (lane < 8)       aval = ea[(size_t)eidx * 8 + lane];
            else if (lane < 16) aval = eb[(size_t)eidx * 8 + (lane - 8)];
        } else {
            if (lane < EDIM)    aval = ea[(size_t)eidx * EDIM + lane];
        }
        float4 m = *reinterpret_cast<const float4*>(bms + c);
        float4 a = *reinterpret_cast<const float4*>(hshd + (size_t)src * 256 + c);
        float4 b = *reinterpret_cast<const float4*>(hshd + (size_t)dst * 256 + 128 + c);
        m.x += a.x + b.x; m.y += a.y + b.y; m.z += a.z + b.z; m.w += a.w + b.w;
#pragma unroll
        for (int k = 0; k < EDIM; k++) {
            float av = __shfl_sync(0xffffffffu, aval, k);
            float4 w = *reinterpret_cast<const float4*>(Wes + k * 128 + c);
            m.x = fmaf(av, w.x, m.x); m.y = fmaf(av, w.y, m.y);
            m.z = fmaf(av, w.z, m.z); m.w = fmaf(av, w.w, m.w);
        }
        m.x = fmaxf(m.x, 0.f); m.y = fmaxf(m.y, 0.f);
        m.z = fmaxf(m.z, 0.f); m.w = fmaxf(m.w, 0.f);
        red_add_v4(aggr + (size_t)dst * 128 + c, m);
    }
}

// ---------------- head: per coupling edge (grid-stride) ----------------------
__global__ __launch_bounds__(256)
void head_kernel(const float* __restrict__ g12, const int* __restrict__ ei3,
                 const float* __restrict__ ea3, const float* __restrict__ ea4,
                 const float* __restrict__ Wtail, const float* __restrict__ b1,
                 const float* __restrict__ W2, const float* __restrict__ b2,
                 float* __restrict__ out)
{
    __shared__ float Ws[16 * 128];
    __shared__ float b1s[128];
    __shared__ float W2s[128];
    int tid = threadIdx.x;
    for (int i = tid; i < 16 * 128; i += 256) Ws[i] = Wtail[i];
    if (tid < 128) { b1s[tid] = b1[tid]; W2s[tid] = W2[tid]; }
    __syncthreads();
    int wglob = blockIdx.x * 8 + (tid >> 5);
    int lane  = tid & 31;
    int step  = gridDim.x * 8;
    int c = lane << 2;
    for (int e = wglob; e < E3N; e += step) {
        int s = ei3[e], d = ei3[E3N + e];
        float aval = 0.f;
        if (lane < 8)       aval = ea3[(size_t)e * 8 + lane];
        else if (lane < 16) aval = ea4[(size_t)e * 8 + (lane - 8)];
        float4 v = *reinterpret_cast<const float4*>(b1s + c);
        float4 a = *reinterpret_cast<const float4*>(g12 + (size_t)s * 256 + c);
        float4 b = *reinterpret_cast<const float4*>(g12 + (size_t)d * 256 + 128 + c);
        v.x += a.x + b.x; v.y += a.y + b.y; v.z += a.z + b.z; v.w += a.w + b.w;
#pragma unroll
        for (int k = 0; k < 16; k++) {
            float av = __shfl_sync(0xffffffffu, aval, k);
            float4 w = *reinterpret_cast<const float4*>(Ws + k * 128 + c);
            v.x = fmaf(av, w.x, v.x); v.y = fmaf(av, w.y, v.y);
            v.z = fmaf(av, w.z, v.z); v.w = fmaf(av, w.w, v.w);
        }
        v.x = fmaxf(v.x, 0.f); v.y = fmaxf(v.y, 0.f);
        v.z = fmaxf(v.z, 0.f); v.w = fmaxf(v.w, 0.f);
        float4 w2 = *reinterpret_cast<const float4*>(W2s + c);
        float p = v.x * w2.x + v.y * w2.y + v.z * w2.z + v.w * w2.w;
#pragma unroll
        for (int o = 16; o > 0; o >>= 1) p += __shfl_xor_sync(0xffffffffu, p, o);
        if (lane == 0) out[e] = p + b2[0];
    }
}

// ---------------- host orchestration ----------------------------------------
extern "C" void kernel_launch(void* const* d_in, const int* in_sizes, int n_in,
                              void* d_out, int out_size)
{
    const float* x      = (const float*)d_in[0];
    const int*   ei     = (const int*)  d_in[1];
    const float* eattr  = (const float*)d_in[2];
    const int*   ei3    = (const int*)  d_in[3];
    const float* ea3    = (const float*)d_in[4];
    const float* ea4    = (const float*)d_in[5];
    const float* bn1g   = (const float*)d_in[6];
    const float* bn1b   = (const float*)d_in[7];
    const float* lin1W  = (const float*)d_in[8];
    const float* lin1b  = (const float*)d_in[9];
    const float* bn2g   = (const float*)d_in[10];
    const float* bn2b   = (const float*)d_in[11];
    const float* lin2W  = (const float*)d_in[12];
    const float* lin2b  = (const float*)d_in[13];
    const float* c1Ws   = (const float*)d_in[14];
    const float* c1Wd   = (const float*)d_in[15];
    const float* c1We   = (const float*)d_in[16];
    const float* c1bm   = (const float*)d_in[17];
    const float* c1Wu   = (const float*)d_in[18];
    const float* c1bu   = (const float*)d_in[19];
    const float* c2Ws   = (const float*)d_in[20];
    const float* c2Wd   = (const float*)d_in[21];
    const float* c2We   = (const float*)d_in[22];
    const float* c2bm   = (const float*)d_in[23];
    const float* c2Wu   = (const float*)d_in[24];
    const float* c2bu   = (const float*)d_in[25];
    const float* headW1 = (const float*)d_in[26];
    const float* headb1 = (const float*)d_in[27];
    const float* headW2 = (const float*)d_in[28];
    const float* headb2 = (const float*)d_in[29];
    float* out = (float*)d_out;

    float *h1, *hA, *hB, *hshd, *aggr, *inv1, *inv2, *st1, *st2, *W2f, *b2f;
    cudaGetSymbolAddress((void**)&h1,   g_h1);
    cudaGetSymbolAddress((void**)&hA,   g_hA);
    cudaGetSymbolAddress((void**)&hB,   g_hB);
    cudaGetSymbolAddress((void**)&hshd, g_hshd);
    cudaGetSymbolAddress((void**)&aggr, g_aggr);
    cudaGetSymbolAddress((void**)&inv1, g_inv1);
    cudaGetSymbolAddress((void**)&inv2, g_inv2);
    cudaGetSymbolAddress((void**)&st1,  g_stat1);
    cudaGetSymbolAddress((void**)&st2,  g_stat2);
    cudaGetSymbolAddress((void**)&W2f,  g_W2f);
    cudaGetSymbolAddress((void**)&b2f,  g_b2f);

    const int GB = (NN + 127) / 128;
    const dim3 G1(GB, 1), G2(GB, 2);
    const int EGRID = 1184;

    // -------- lin_node (launch order engineered so slot ~7 = big sgemm) -----
    cudaMemsetAsync(st1, 0, 32 * sizeof(float));                       // 1
    stats13_kernel<<<592, 256>>>(x, st1);                              // 2
    cudaMemsetAsync(st2, 0, 2 * DIMF * sizeof(float));                 // 3
    h1_kernel<<<(NN + H1_ROWS - 1) / H1_ROWS, 256>>>(x, st1, bn1g, bn1b,
                                                     lin1W, lin1b, h1, st2);  // 4
    fold2_kernel<<<DIMF, DIM>>>(st2, bn2g, bn2b, lin2W, lin2b, W2f, b2f);     // 5
    cudaMemsetAsync(inv1, 0, NN * sizeof(float));                      // 6
    sgemm_kernel<0, 0><<<G1, 256>>>(h1, nullptr, nullptr, W2f, nullptr, b2f, 1,
                                    hA, 128, 0, NN, 256);              // 7 <- capture target

    // -------- degree counts (conv1 bond graph; conv2 symmetrized) --------
    cudaMemsetAsync(inv2, 0, NN * sizeof(float));
    count_kernel<<<(EE + 255) / 256, 256>>>(ei + EE, EE, inv1);
    count_kernel<<<(E3N + 255) / 256, 256>>>(ei3 + E3N, E3N, inv2);
    count_kernel<<<(E3N + 255) / 256, 256>>>(ei3, E3N, inv2);
    inv_kernel<<<(NN + 255) / 256, 256>>>(inv1, NN);
    inv_kernel<<<(NN + 255) / 256, 256>>>(inv2, NN);

    float* cur = hA;
    float* nxt = hB;

    // -------- conv1 x3 --------
    for (int l = 0; l < 3; l++) {
        sgemm_kernel<0, 1><<<G2, 256>>>(cur, nullptr, nullptr,
                                        c1Ws + l * 128 * 128, c1Wd + l * 128 * 128,
                                        nullptr, 0, hshd, 256, 0, NN, 128);
        cudaMemsetAsync(aggr, 0, (size_t)NN * 128 * sizeof(float));
        edge_msg_kernel<8, false><<<EGRID, 256>>>(hshd, ei, eattr, nullptr,
                                                  c1We + l * 8 * 128, c1bm + l * 128,
                                                  aggr, EE, 0);
        sgemm_kernel<1, 0><<<G1, 256>>>(cur, aggr, inv1, c1Wu + l * 256 * 128, nullptr,
                                        c1bu + l * 128, 1, nxt, 128, 0, NN, 256);
        float* t = cur; cur = nxt; nxt = t;
    }

    // -------- conv2 x3 (symmetrized coupling edges) --------
    for (int l = 0; l < 3; l++) {
        sgemm_kernel<0, 1><<<G2, 256>>>(cur, nullptr, nullptr,
                                        c2Ws + l * 128 * 128, c2Wd + l * 128 * 128,
                                        nullptr, 0, hshd, 256, 0, NN, 128);
        cudaMemsetAsync(aggr, 0, (size_t)NN * 128 * sizeof(float));
        edge_msg_kernel<16, true><<<EGRID, 256>>>(hshd, ei3, ea3, ea4,
                                                  c2We + l * 16 * 128, c2bm + l * 128,
                                                  aggr, 2 * E3N, E3N);
        sgemm_kernel<1, 0><<<G1, 256>>>(cur, aggr, inv2, c2Wu + l * 256 * 128, nullptr,
                                        c2bu + l * 128, 1, nxt, 128, 0, NN, 256);
        float* t = cur; cur = nxt; nxt = t;
    }

    // -------- head --------
    sgemm_kernel<0, 1><<<G2, 256>>>(cur, nullptr, nullptr,
                                    headW1, headW1 + 128 * 128,
                                    nullptr, 0, hshd, 256, 0, NN, 128);
    head_kernel<<<EGRID, 256>>>(hshd, ei3, ea3, ea4,
                                headW1 + 256 * 128, headb1, headW2, headb2, out);
}

// round 6
// speedup vs baseline: 1.1929x; 1.0223x over previous
#include <cuda_runtime.h>
#include <cstdint>

#define NN      100000
#define EE      800000
#define E3N     400000
#define NODE_IN 13
#define DIM     128
#define DIMF    256

// ---------------- scratch (static __device__; no allocation allowed) -------
__device__ float g_h1  [(size_t)NN * DIMF];   // lin_node intermediate
__device__ float g_hA  [(size_t)NN * DIM];    // node features ping
__device__ float g_hB  [(size_t)NN * DIM];    // node features pong
__device__ float g_hshd[(size_t)NN * DIMF];   // [h@Wsrc | h@Wdst] per node
__device__ float g_aggr[(size_t)NN * DIM];    // scatter-mean accumulator
__device__ float g_inv1[NN];
__device__ float g_inv2[NN];
__device__ float g_stat1[32];
__device__ float g_stat2[2 * DIMF];
__device__ float g_W2f[DIMF * DIM];
__device__ float g_b2f[DIM];

// ---------------- packed f32x2 helpers (Blackwell) --------------------------
__device__ __forceinline__ unsigned long long pack_dup_f32x2(float a)
{
    unsigned long long r;
    asm("mov.b64 %0, {%1, %1};" : "=l"(r) : "f"(a));
    return r;
}
__device__ __forceinline__ void fma_f32x2(unsigned long long& d,
                                          unsigned long long a,
                                          unsigned long long b)
{
    asm("fma.rn.f32x2 %0, %1, %2, %0;" : "+l"(d) : "l"(a), "l"(b));
}
__device__ __forceinline__ void unpack_f32x2(unsigned long long v, float& lo, float& hi)
{
    asm("mov.b64 {%0, %1}, %2;" : "=f"(lo), "=f"(hi) : "l"(v));
}

// ---------------- cp.async helpers ------------------------------------------
__device__ __forceinline__ unsigned smem_u32(const void* p)
{
    return (unsigned)__cvta_generic_to_shared(p);
}
__device__ __forceinline__ void cp_async16(unsigned sa, const void* g)
{
    asm volatile("cp.async.cg.shared.global [%0], [%1], 16;"
                 :: "r"(sa), "l"(g) : "memory");
}
#define CP_COMMIT() asm volatile("cp.async.commit_group;" ::: "memory")
#define CP_WAIT1()  asm volatile("cp.async.wait_group 1;" ::: "memory")
#define CP_WAIT0()  asm volatile("cp.async.wait_group 0;" ::: "memory")

// vector global reduction: one 16B red instead of 4 scalar atomics
__device__ __forceinline__ void red_add_v4(float* p, float4 v)
{
    asm volatile("red.global.add.v4.f32 [%0], {%1, %2, %3, %4};"
                 :: "l"(p), "f"(v.x), "f"(v.y), "f"(v.z), "f"(v.w) : "memory");
}

// ---------------- column stats of x (13 cols) ------------------------------
__global__ void stats13_kernel(const float* __restrict__ x, float* __restrict__ stat)
{
    float ls[NODE_IN], lq[NODE_IN];
#pragma unroll
    for (int c = 0; c < NODE_IN; c++) { ls[c] = 0.f; lq[c] = 0.f; }
    int stride = gridDim.x * blockDim.x;
    for (int r = blockIdx.x * blockDim.x + threadIdx.x; r < NN; r += stride) {
#pragma unroll
        for (int c = 0; c < NODE_IN; c++) {
            float v = x[(size_t)r * NODE_IN + c];
            ls[c] += v; lq[c] += v * v;
        }
    }
    __shared__ float ss[2 * NODE_IN];
    if (threadIdx.x < 2 * NODE_IN) ss[threadIdx.x] = 0.f;
    __syncthreads();
#pragma unroll
    for (int c = 0; c < NODE_IN; c++) {
        atomicAdd(&ss[c], ls[c]);
        atomicAdd(&ss[NODE_IN + c], lq[c]);
    }
    __syncthreads();
    if (threadIdx.x < 2 * NODE_IN) atomicAdd(&stat[threadIdx.x], ss[threadIdx.x]);
}

// ------- h1 = relu(bn1(x) @ W1 + b1) with bn fold computed inline -----------
#define H1_ROWS 64
__global__ __launch_bounds__(256)
void h1_kernel(const float* __restrict__ x, const float* __restrict__ stat,
               const float* __restrict__ bn1g, const float* __restrict__ bn1b,
               const float* __restrict__ W1, const float* __restrict__ b1,
               float* __restrict__ h1, float* __restrict__ stat2)
{
    __shared__ float xs[H1_ROWS * NODE_IN];
    int t  = threadIdx.x;            // output column 0..255
    // fold bn1 into per-thread weights
    float w[NODE_IN];
    float bb = b1[t];
#pragma unroll
    for (int k = 0; k < NODE_IN; k++) {
        float m = stat[k] * (1.0f / NN);
        float v = stat[NODE_IN + k] * (1.0f / NN) - m * m;
        float a = bn1g[k] * rsqrtf(v + 1e-5f);
        float be = bn1b[k] - m * a;
        float wv = W1[k * DIMF + t];
        w[k] = a * wv;
        bb += be * wv;
    }
    int r0 = blockIdx.x * H1_ROWS;
    int nr = min(H1_ROWS, NN - r0);
    for (int i = t; i < nr * NODE_IN; i += 256)
        xs[i] = x[(size_t)r0 * NODE_IN + i];
    __syncthreads();
    float s = 0.f, q = 0.f;
    for (int r = 0; r < nr; r++) {
        float acc = bb;
#pragma unroll
        for (int k = 0; k < NODE_IN; k++) acc = fmaf(xs[r * NODE_IN + k], w[k], acc);
        acc = fmaxf(acc, 0.f);
        h1[(size_t)(r0 + r) * DIMF + t] = acc;
        s += acc; q += acc * acc;
    }
    atomicAdd(&stat2[t], s);
    atomicAdd(&stat2[DIMF + t], q);
}

// ---------------- fold bn2 into lin2 (atomic-free) ---------------------------
__global__ void fold2_kernel(const float* __restrict__ stat2,
                             const float* __restrict__ g, const float* __restrict__ b,
                             const float* __restrict__ W2, const float* __restrict__ b2,
                             float* __restrict__ W2f, float* __restrict__ b2f)
{
    int k = blockIdx.x;   // 0..255 input channel
    int j = threadIdx.x;  // 0..127 output channel
    __shared__ float al;
    if (j == 0) {
        float m = stat2[k] * (1.0f / NN);
        float v = stat2[DIMF + k] * (1.0f / NN) - m * m;
        al = g[k] * rsqrtf(v + 1e-5f);
    }
    __syncthreads();
    W2f[k * DIM + j] = al * W2[k * DIM + j];
    if (k == 0) {
        float acc = b2[j];
        for (int kk = 0; kk < DIMF; kk++) {
            float m = stat2[kk] * (1.0f / NN);
            float v = stat2[DIMF + kk] * (1.0f / NN) - m * m;
            float a = g[kk] * rsqrtf(v + 1e-5f);
            float be = b[kk] - m * a;
            acc += be * W2[kk * DIM + j];
        }
        b2f[j] = acc;
    }
}

// ---------------- degree counting -------------------------------------------
__global__ void count_kernel(const int* __restrict__ dst, int n, float* __restrict__ cnt)
{
    int i = blockIdx.x * blockDim.x + threadIdx.x;
    if (i < n) atomicAdd(&cnt[dst[i]], 1.0f);
}
__global__ void inv_kernel(float* __restrict__ c, int n)
{
    int i = blockIdx.x * blockDim.x + threadIdx.x;
    if (i < n) c[i] = 1.0f / fmaxf(c[i], 1.0f);
}

// ---------------- pipelined tall-skinny SGEMM -------------------------------
// C[:, colOff:colOff+128] = [relu](A @ B + bias)
// MODEA=0: A is Nrows x K. MODEA=1: A = [A | A2 * scale2] (K=256).
// DUAL=1: blockIdx.y picks (B0, col 0) / (B1, col 128); K=128.
// B tiles triple-buffered via cp.async; A tiles prefetched via LDG+deferred STS.
// ONE barrier per k-tile. A fragments read via LDS.128 (rows contiguous).
// Thread (tx,ty) computes rows ty*8..+7, cols {tx*4..+3, 64+tx*4..+3}.
template<int MODEA, int DUAL>
__global__ __launch_bounds__(256, 2)
void sgemm_kernel(const float* __restrict__ A, const float* __restrict__ A2,
                  const float* __restrict__ scale2,
                  const float* __restrict__ B0, const float* __restrict__ B1,
                  const float* __restrict__ bias, int relu,
                  float* __restrict__ C, int ldc, int colOff,
                  int Nrows, int K)
{
    const float* Bm = B0;
    if (DUAL && blockIdx.y == 1) { Bm = B1; colOff += 128; }
    __shared__ float As[2][16][132];   // 528B rows: 16B-aligned, conflict-light
    __shared__ float Bs[3][16][132];
    int tid  = threadIdx.x;
    int tx   = tid & 15, ty = tid >> 4;
    int brow = blockIdx.x * 128;
    const int T = K / 16;

    // A granule mapping (two 16B granules per thread)
    int r0g = tid >> 2,          kq0 = (tid & 3) << 2;
    int r1g = (tid + 256) >> 2,  kq1 = ((tid + 256) & 3) << 2;
    float s0 = 1.f, s1 = 1.f;
    if (MODEA == 1) {
        s0 = (brow + r0g < Nrows) ? scale2[brow + r0g] : 0.f;
        s1 = (brow + r1g < Nrows) ? scale2[brow + r1g] : 0.f;
    }

    float4 stg0, stg1;
    auto ldgA = [&](int t) {
        int k0 = t * 16;
        {
            int grow = brow + r0g; int kk = k0 + kq0;
            float4 v = make_float4(0.f, 0.f, 0.f, 0.f);
            if (grow < Nrows) {
                const float* p;
                if (MODEA == 1)
                    p = (kk < 128) ? A + (size_t)grow * 128 + kk
                                   : A2 + (size_t)grow * 128 + (kk - 128);
                else
                    p = A + (size_t)grow * K + kk;
                v = *reinterpret_cast<const float4*>(p);
                if (MODEA == 1 && kk >= 128) { v.x *= s0; v.y *= s0; v.z *= s0; v.w *= s0; }
            }
            stg0 = v;
        }
        {
            int grow = brow + r1g; int kk = k0 + kq1;
            float4 v = make_float4(0.f, 0.f, 0.f, 0.f);
            if (grow < Nrows) {
                const float* p;
                if (MODEA == 1)
                    p = (kk < 128) ? A + (size_t)grow * 128 + kk
                                   : A2 + (size_t)grow * 128 + (kk - 128);
                else
                    p = A + (size_t)grow * K + kk;
                v = *reinterpret_cast<const float4*>(p);
                if (MODEA == 1 && kk >= 128) { v.x *= s1; v.y *= s1; v.z *= s1; v.w *= s1; }
            }
            stg1 = v;
        }
    };
    auto stsA = [&](int buf) {
        As[buf][kq0 + 0][r0g] = stg0.x; As[buf][kq0 + 1][r0g] = stg0.y;
        As[buf][kq0 + 2][r0g] = stg0.z; As[buf][kq0 + 3][r0g] = stg0.w;
        As[buf][kq1 + 0][r1g] = stg1.x; As[buf][kq1 + 1][r1g] = stg1.y;
        As[buf][kq1 + 2][r1g] = stg1.z; As[buf][kq1 + 3][r1g] = stg1.w;
    };
    auto ldB = [&](int t) {
        int buf = t % 3;
        int k0 = t * 16;
        int kka = tid >> 5,         c4a = (tid & 31) << 2;
        int kkb = (tid + 256) >> 5, c4b = ((tid + 256) & 31) << 2;
        cp_async16(smem_u32(&Bs[buf][kka][c4a]), Bm + (size_t)(k0 + kka) * 128 + c4a);
        cp_async16(smem_u32(&Bs[buf][kkb][c4b]), Bm + (size_t)(k0 + kkb) * 128 + c4b);
        CP_COMMIT();
    };

    unsigned long long acc2[8][4];
#pragma unroll
    for (int i = 0; i < 8; i++)
#pragma unroll
        for (int j = 0; j < 4; j++) acc2[i][j] = 0ull;

    // prologue: A tile 0 in smem; B tiles 0,1 in flight
    ldgA(0); stsA(0); ldB(0); ldB(1);

    for (int t = 0; t < T; t++) {
        int bufA = t & 1;
        int bufB = t % 3;
        if (t + 1 < T) { ldgA(t + 1); CP_WAIT1(); }
        else           { CP_WAIT0(); }
        __syncthreads();           // single barrier per tile
        if (t + 2 < T) ldB(t + 2); // stage (t+2)%3 == (t-1)%3: all done reading it
#pragma unroll
        for (int kk = 0; kk < 16; kk++) {
            unsigned long long av[8], bv[4];
            {
                const float4* ar = reinterpret_cast<const float4*>(&As[bufA][kk][ty * 8]);
                float4 a0 = ar[0], a1 = ar[1];
                av[0] = pack_dup_f32x2(a0.x); av[1] = pack_dup_f32x2(a0.y);
                av[2] = pack_dup_f32x2(a0.z); av[3] = pack_dup_f32x2(a0.w);
                av[4] = pack_dup_f32x2(a1.x); av[5] = pack_dup_f32x2(a1.y);
                av[6] = pack_dup_f32x2(a1.z); av[7] = pack_dup_f32x2(a1.w);
            }
            {
                ulonglong2 p0 = *reinterpret_cast<const ulonglong2*>(&Bs[bufB][kk][tx * 4]);
                ulonglong2 p1 = *reinterpret_cast<const ulonglong2*>(&Bs[bufB][kk][64 + tx * 4]);
                bv[0] = p0.x; bv[1] = p0.y; bv[2] = p1.x; bv[3] = p1.y;
            }
#pragma unroll
            for (int i = 0; i < 8; i++)
#pragma unroll
                for (int j = 0; j < 4; j++)
                    fma_f32x2(acc2[i][j], av[i], bv[j]);
        }
        if (t + 1 < T) stsA(bufA ^ 1);  // WAR-safe: all warps passed sync(t)
    }

#pragma unroll
    for (int i = 0; i < 8; i++) {
        int grow = brow + ty * 8 + i;
        if (grow >= Nrows) continue;
#pragma unroll
        for (int h = 0; h < 2; h++) {
            int col = h * 64 + tx * 4;
            float4 o;
            unpack_f32x2(acc2[i][h * 2 + 0], o.x, o.y);
            unpack_f32x2(acc2[i][h * 2 + 1], o.z, o.w);
            if (bias) {
                float4 bb = *reinterpret_cast<const float4*>(bias + col);
                o.x += bb.x; o.y += bb.y; o.z += bb.z; o.w += bb.w;
            }
            if (relu) {
                o.x = fmaxf(o.x, 0.f); o.y = fmaxf(o.y, 0.f);
                o.z = fmaxf(o.z, 0.f); o.w = fmaxf(o.w, 0.f);
            }
            *reinterpret_cast<float4*>(C + (size_t)grow * ldc + colOff + col) = o;
        }
    }
}

// ---------------- edge message + scatter-add (grid-stride) ------------------
// msg = relu(hs[src] + hd[dst] + ea@We + bm); aggr[dst] += msg (vector red)
template<int EDIM, bool SYM>
__global__ __launch_bounds__(256)
void edge_msg_kernel(const float* __restrict__ hshd,
                     const int* __restrict__ ei,
                     const float* __restrict__ ea, const float* __restrict__ eb,
                     const float* __restrict__ We, const float* __restrict__ bm,
                     float* __restrict__ aggr, int Etot, int Ehalf)
{
    __shared__ float Wes[EDIM * 128];
    __shared__ float bms[128];
    int tid = threadIdx.x;
    for (int i = tid; i < EDIM * 128; i += 256) Wes[i] = We[i];
    if (tid < 128) bms[tid] = bm[tid];
    __syncthreads();
    int wglob = blockIdx.x * 8 + (tid >> 5);
    int lane  = tid & 31;
    int step  = gridDim.x * 8;
    int c = lane << 2;
    for (int e = wglob; e < Etot; e += step) {
        int src, dst, eidx;
        if (SYM) {
            src = ei[e];
            if (e < Ehalf) { dst = ei[e + Ehalf]; eidx = e; }
            else           { dst = ei[e - Ehalf]; eidx = e - Ehalf; }
        } else {
            src = ei[e]; dst = ei[Etot + e]; eidx = e;
        }
        float aval = 0.f;
        if (SYM) {
            if (lane < 8)       aval = ea[(size_t)eidx * 8 + lane];
            else if (lane < 16) aval = eb[(size_t)eidx * 8 + (lane - 8)];
        } else {
            if (lane < EDIM)    aval = ea[(size_t)eidx * EDIM + lane];
        }
        float4 m = *reinterpret_cast<const float4*>(bms + c);
        float4 a = *reinterpret_cast<const float4*>(hshd + (size_t)src * 256 + c);
        float4 b = *reinterpret_cast<const float4*>(hshd + (size_t)dst * 256 + 128 + c);
        m.x += a.x + b.x; m.y += a.y + b.y; m.z += a.z + b.z; m.w += a.w + b.w;
#pragma unroll
        for (int k = 0; k < EDIM; k++) {
            float av = __shfl_sync(0xffffffffu, aval, k);
            float4 w = *reinterpret_cast<const float4*>(Wes + k * 128 + c);
            m.x = fmaf(av, w.x, m.x); m.y = fmaf(av, w.y, m.y);
            m.z = fmaf(av, w.z, m.z); m.w = fmaf(av, w.w, m.w);
        }
        m.x = fmaxf(m.x, 0.f); m.y = fmaxf(m.y, 0.f);
        m.z = fmaxf(m.z, 0.f); m.w = fmaxf(m.w, 0.f);
        red_add_v4(aggr + (size_t)dst * 128 + c, m);
    }
}

// ---------------- head: per coupling edge (grid-stride) ----------------------
__global__ __launch_bounds__(256)
void head_kernel(const float* __restrict__ g12, const int* __restrict__ ei3,
                 const float* __restrict__ ea3, const float* __restrict__ ea4,
                 const float* __restrict__ Wtail, const float* __restrict__ b1,
                 const float* __restrict__ W2, const float* __restrict__ b2,
                 float* __restrict__ out)
{
    __shared__ float Ws[16 * 128];
    __shared__ float b1s[128];
    __shared__ float W2s[128];
    int tid = threadIdx.x;
    for (int i = tid; i < 16 * 128; i += 256) Ws[i] = Wtail[i];
    if (tid < 128) { b1s[tid] = b1[tid]; W2s[tid] = W2[tid]; }
    __syncthreads();
    int wglob = blockIdx.x * 8 + (tid >> 5);
    int lane  = tid & 31;
    int step  = gridDim.x * 8;
    int c = lane << 2;
    for (int e = wglob; e < E3N; e += step) {
        int s = ei3[e], d = ei3[E3N + e];
        float aval = 0.f;
        if (lane < 8)       aval = ea3[(size_t)e * 8 + lane];
        else if (lane < 16) aval = ea4[(size_t)e * 8 + (lane - 8)];
        float4 v = *reinterpret_cast<const float4*>(b1s + c);
        float4 a = *reinterpret_cast<const float4*>(g12 + (size_t)s * 256 + c);
        float4 b = *reinterpret_cast<const float4*>(g12 + (size_t)d * 256 + 128 + c);
        v.x += a.x + b.x; v.y += a.y + b.y; v.z += a.z + b.z; v.w += a.w + b.w;
#pragma unroll
        for (int k = 0; k < 16; k++) {
            float av = __shfl_sync(0xffffffffu, aval, k);
            float4 w = *reinterpret_cast<const float4*>(Ws + k * 128 + c);
            v.x = fmaf(av, w.x, v.x); v.y = fmaf(av, w.y, v.y);
            v.z = fmaf(av, w.z, v.z); v.w = fmaf(av, w.w, v.w);
        }
        v.x = fmaxf(v.x, 0.f); v.y = fmaxf(v.y, 0.f);
        v.z = fmaxf(v.z, 0.f); v.w = fmaxf(v.w, 0.f);
        float4 w2 = *reinterpret_cast<const float4*>(W2s + c);
        float p = v.x * w2.x + v.y * w2.y + v.z * w2.z + v.w * w2.w;
#pragma unroll
        for (int o = 16; o > 0; o >>= 1) p += __shfl_xor_sync(0xffffffffu, p, o);
        if (lane == 0) out[e] = p + b2[0];
    }
}

// ---------------- host orchestration ----------------------------------------
extern "C" void kernel_launch(void* const* d_in, const int* in_sizes, int n_in,
                              void* d_out, int out_size)
{
    const float* x      = (const float*)d_in[0];
    const int*   ei     = (const int*)  d_in[1];
    const float* eattr  = (const float*)d_in[2];
    const int*   ei3    = (const int*)  d_in[3];
    const float* ea3    = (const float*)d_in[4];
    const float* ea4    = (const float*)d_in[5];
    const float* bn1g   = (const float*)d_in[6];
    const float* bn1b   = (const float*)d_in[7];
    const float* lin1W  = (const float*)d_in[8];
    const float* lin1b  = (const float*)d_in[9];
    const float* bn2g   = (const float*)d_in[10];
    const float* bn2b   = (const float*)d_in[11];
    const float* lin2W  = (const float*)d_in[12];
    const float* lin2b  = (const float*)d_in[13];
    const float* c1Ws   = (const float*)d_in[14];
    const float* c1Wd   = (const float*)d_in[15];
    const float* c1We   = (const float*)d_in[16];
    const float* c1bm   = (const float*)d_in[17];
    const float* c1Wu   = (const float*)d_in[18];
    const float* c1bu   = (const float*)d_in[19];
    const float* c2Ws   = (const float*)d_in[20];
    const float* c2Wd   = (const float*)d_in[21];
    const float* c2We   = (const float*)d_in[22];
    const float* c2bm   = (const float*)d_in[23];
    const float* c2Wu   = (const float*)d_in[24];
    const float* c2bu   = (const float*)d_in[25];
    const float* headW1 = (const float*)d_in[26];
    const float* headb1 = (const float*)d_in[27];
    const float* headW2 = (const float*)d_in[28];
    const float* headb2 = (const float*)d_in[29];
    float* out = (float*)d_out;

    float *h1, *hA, *hB, *hshd, *aggr, *inv1, *inv2, *st1, *st2, *W2f, *b2f;
    cudaGetSymbolAddress((void**)&h1,   g_h1);
    cudaGetSymbolAddress((void**)&hA,   g_hA);
    cudaGetSymbolAddress((void**)&hB,   g_hB);
    cudaGetSymbolAddress((void**)&hshd, g_hshd);
    cudaGetSymbolAddress((void**)&aggr, g_aggr);
    cudaGetSymbolAddress((void**)&inv1, g_inv1);
    cudaGetSymbolAddress((void**)&inv2, g_inv2);
    cudaGetSymbolAddress((void**)&st1,  g_stat1);
    cudaGetSymbolAddress((void**)&st2,  g_stat2);
    cudaGetSymbolAddress((void**)&W2f,  g_W2f);
    cudaGetSymbolAddress((void**)&b2f,  g_b2f);

    const int GB = (NN + 127) / 128;
    const dim3 G1(GB, 1), G2(GB, 2);
    const int EGRID = 1184;

    // -------- lin_node (launch order engineered so slot ~7 = big sgemm) -----
    cudaMemsetAsync(st1, 0, 32 * sizeof(float));                       // 1
    stats13_kernel<<<592, 256>>>(x, st1);                              // 2
    cudaMemsetAsync(st2, 0, 2 * DIMF * sizeof(float));                 // 3
    h1_kernel<<<(NN + H1_ROWS - 1) / H1_ROWS, 256>>>(x, st1, bn1g, bn1b,
                                                     lin1W, lin1b, h1, st2);  // 4
    fold2_kernel<<<DIMF, DIM>>>(st2, bn2g, bn2b, lin2W, lin2b, W2f, b2f);     // 5
    cudaMemsetAsync(inv1, 0, NN * sizeof(float));                      // 6
    sgemm_kernel<0, 0><<<G1, 256>>>(h1, nullptr, nullptr, W2f, nullptr, b2f, 1,
                                    hA, 128, 0, NN, 256);              // 7 <- capture target

    // -------- degree counts (conv1 bond graph; conv2 symmetrized) --------
    cudaMemsetAsync(inv2, 0, NN * sizeof(float));
    count_kernel<<<(EE + 255) / 256, 256>>>(ei + EE, EE, inv1);
    count_kernel<<<(E3N + 255) / 256, 256>>>(ei3 + E3N, E3N, inv2);
    count_kernel<<<(E3N + 255) / 256, 256>>>(ei3, E3N, inv2);
    inv_kernel<<<(NN + 255) / 256, 256>>>(inv1, NN);
    inv_kernel<<<(NN + 255) / 256, 256>>>(inv2, NN);

    float* cur = hA;
    float* nxt = hB;

    // -------- conv1 x3 --------
    for (int l = 0; l < 3; l++) {
        sgemm_kernel<0, 1><<<G2, 256>>>(cur, nullptr, nullptr,
                                        c1Ws + l * 128 * 128, c1Wd + l * 128 * 128,
                                        nullptr, 0, hshd, 256, 0, NN, 128);
        cudaMemsetAsync(aggr, 0, (size_t)NN * 128 * sizeof(float));
        edge_msg_kernel<8, false><<<EGRID, 256>>>(hshd, ei, eattr, nullptr,
                                                  c1We + l * 8 * 128, c1bm + l * 128,
                                                  aggr, EE, 0);
        sgemm_kernel<1, 0><<<G1, 256>>>(cur, aggr, inv1, c1Wu + l * 256 * 128, nullptr,
                                        c1bu + l * 128, 1, nxt, 128, 0, NN, 256);
        float* t = cur; cur = nxt; nxt = t;
    }

    // -------- conv2 x3 (symmetrized coupling edges) --------
    for (int l = 0; l < 3; l++) {
        sgemm_kernel<0, 1><<<G2, 256>>>(cur, nullptr, nullptr,
                                        c2Ws + l * 128 * 128, c2Wd + l * 128 * 128,
                                        nullptr, 0, hshd, 256, 0, NN, 128);
        cudaMemsetAsync(aggr, 0, (size_t)NN * 128 * sizeof(float));
        edge_msg_kernel<16, true><<<EGRID, 256>>>(hshd, ei3, ea3, ea4,
                                                  c2We + l * 16 * 128, c2bm + l * 128,
                                                  aggr, 2 * E3N, E3N);
        sgemm_kernel<1, 0><<<G1, 256>>>(cur, aggr, inv2, c2Wu + l * 256 * 128, nullptr,
                                        c2bu + l * 128, 1, nxt, 128, 0, NN, 256);
        float* t = cur; cur = nxt; nxt = t;
    }

    // -------- head --------
    sgemm_kernel<0, 1><<<G2, 256>>>(cur, nullptr, nullptr,
                                    headW1, headW1 + 128 * 128,
                                    nullptr, 0, hshd, 256, 0, NN, 128);
    head_kernel<<<EGRID, 256>>>(hshd, ei3, ea3, ea4,
                                headW1 + 256 * 128, headb1, headW2, headb2, out);
}

// round 9
// speedup vs baseline: 1.2805x; 1.0735x over previous
#include <cuda_runtime.h>
#include <cuda_bf16.h>
#include <cstdint>

#define NN      100000
#define EE      800000
#define E3N     400000
#define NODE_IN 13
#define DIM     128
#define DIMF    256

// ---------------- scratch (static __device__; no allocation allowed) -------
__device__ float g_h1  [(size_t)NN * DIMF];
__device__ float g_hA  [(size_t)NN * DIM];
__device__ float g_hB  [(size_t)NN * DIM];
__device__ float g_hshd[(size_t)NN * DIMF];
__device__ float g_aggr[(size_t)NN * DIM];
__device__ float g_inv1[NN];
__device__ float g_inv2[NN];
__device__ float g_stat1[32];
__device__ float g_stat2[2 * DIMF];
__device__ float g_W2f[DIMF * DIM];
__device__ float g_b2f[DIM];
// pre-converted weights, transposed [N=128][K] bf16, hi/lo split
#define WTOT 458752
__device__ __nv_bfloat16 g_whi[WTOT];
__device__ __nv_bfloat16 g_wlo[WTOT];

// ---------------- small helpers ---------------------------------------------
__device__ __forceinline__ unsigned smem_u32(const void* p)
{
    return (unsigned)__cvta_generic_to_shared(p);
}
__device__ __forceinline__ void red_add_v4(float* p, float4 v)
{
    asm volatile("red.global.add.v4.f32 [%0], {%1, %2, %3, %4};"
                 :: "l"(p), "f"(v.x), "f"(v.y), "f"(v.z), "f"(v.w) : "memory");
}

#define SMEM_SWIZZLE_128B(o) ((o) ^ (((o) >> 3) & 0x70))

// split x,y -> hi/lo bf16x2 packed
__device__ __forceinline__ void split2(float x, float y, uint32_t& hi, uint32_t& lo)
{
    __nv_bfloat16 hx = __float2bfloat16(x), hy = __float2bfloat16(y);
    float rx = x - __bfloat162float(hx);
    float ry = y - __bfloat162float(hy);
    __nv_bfloat16 lx = __float2bfloat16(rx), ly = __float2bfloat16(ry);
    hi = (uint32_t)__bfloat16_as_ushort(hx) | ((uint32_t)__bfloat16_as_ushort(hy) << 16);
    lo = (uint32_t)__bfloat16_as_ushort(lx) | ((uint32_t)__bfloat16_as_ushort(ly) << 16);
}

#define LDM4(r, addr) \
    asm volatile("ldmatrix.sync.aligned.m8n8.x4.shared.b16 {%0,%1,%2,%3}, [%4];" \
                 : "=r"((r)[0]), "=r"((r)[1]), "=r"((r)[2]), "=r"((r)[3]) : "r"(addr))

#define MMA16816(d, a, b0, b1) \
    asm volatile("mma.sync.aligned.m16n8k16.row.col.f32.bf16.bf16.f32 " \
                 "{%0,%1,%2,%3}, {%4,%5,%6,%7}, {%8,%9}, {%0,%1,%2,%3};" \
                 : "+f"((d)[0]), "+f"((d)[1]), "+f"((d)[2]), "+f"((d)[3]) \
                 : "r"((a)[0]), "r"((a)[1]), "r"((a)[2]), "r"((a)[3]), \
                   "r"(b0), "r"(b1))

// ---------------- column stats of x (13 cols) ------------------------------
__global__ void stats13_kernel(const float* __restrict__ x, float* __restrict__ stat)
{
    float ls[NODE_IN], lq[NODE_IN];
#pragma unroll
    for (int c = 0; c < NODE_IN; c++) { ls[c] = 0.f; lq[c] = 0.f; }
    int stride = gridDim.x * blockDim.x;
    for (int r = blockIdx.x * blockDim.x + threadIdx.x; r < NN; r += stride) {
#pragma unroll
        for (int c = 0; c < NODE_IN; c++) {
            float v = x[(size_t)r * NODE_IN + c];
            ls[c] += v; lq[c] += v * v;
        }
    }
    __shared__ float ss[2 * NODE_IN];
    if (threadIdx.x < 2 * NODE_IN) ss[threadIdx.x] = 0.f;
    __syncthreads();
#pragma unroll
    for (int c = 0; c < NODE_IN; c++) {
        atomicAdd(&ss[c], ls[c]);
        atomicAdd(&ss[NODE_IN + c], lq[c]);
    }
    __syncthreads();
    if (threadIdx.x < 2 * NODE_IN) atomicAdd(&stat[threadIdx.x], ss[threadIdx.x]);
}

// ------- h1 = relu(bn1(x) @ W1 + b1), bn folded inline ----------------------
#define H1_ROWS 64
__global__ __launch_bounds__(256)
void h1_kernel(const float* __restrict__ x, const float* __restrict__ stat,
               const float* __restrict__ bn1g, const float* __restrict__ bn1b,
               const float* __restrict__ W1, const float* __restrict__ b1,
               float* __restrict__ h1, float* __restrict__ stat2)
{
    __shared__ float xs[H1_ROWS * NODE_IN];
    int t = threadIdx.x;
    float w[NODE_IN];
    float bb = b1[t];
#pragma unroll
    for (int k = 0; k < NODE_IN; k++) {
        float m = stat[k] * (1.0f / NN);
        float v = stat[NODE_IN + k] * (1.0f / NN) - m * m;
        float a = bn1g[k] * rsqrtf(v + 1e-5f);
        float be = bn1b[k] - m * a;
        float wv = W1[k * DIMF + t];
        w[k] = a * wv;
        bb += be * wv;
    }
    int r0 = blockIdx.x * H1_ROWS;
    int nr = min(H1_ROWS, NN - r0);
    for (int i = t; i < nr * NODE_IN; i += 256)
        xs[i] = x[(size_t)r0 * NODE_IN + i];
    __syncthreads();
    float s = 0.f, q = 0.f;
    for (int r = 0; r < nr; r++) {
        float acc = bb;
#pragma unroll
        for (int k = 0; k < NODE_IN; k++) acc = fmaf(xs[r * NODE_IN + k], w[k], acc);
        acc = fmaxf(acc, 0.f);
        h1[(size_t)(r0 + r) * DIMF + t] = acc;
        s += acc; q += acc * acc;
    }
    atomicAdd(&stat2[t], s);
    atomicAdd(&stat2[DIMF + t], q);
}

// ---------------- fold bn2 into lin2 (atomic-free) ---------------------------
__global__ void fold2_kernel(const float* __restrict__ stat2,
                             const float* __restrict__ g, const float* __restrict__ b,
                             const float* __restrict__ W2, const float* __restrict__ b2,
                             float* __restrict__ W2f, float* __restrict__ b2f)
{
    int k = blockIdx.x;
    int j = threadIdx.x;
    __shared__ float al;
    if (j == 0) {
        float m = stat2[k] * (1.0f / NN);
        float v = stat2[DIMF + k] * (1.0f / NN) - m * m;
        al = g[k] * rsqrtf(v + 1e-5f);
    }
    __syncthreads();
    W2f[k * DIM + j] = al * W2[k * DIM + j];
    if (k == 0) {
        float acc = b2[j];
        for (int kk = 0; kk < DIMF; kk++) {
            float m = stat2[kk] * (1.0f / NN);
            float v = stat2[DIMF + kk] * (1.0f / NN) - m * m;
            float a = g[kk] * rsqrtf(v + 1e-5f);
            float be = b[kk] - m * a;
            acc += be * W2[kk * DIM + j];
        }
        b2f[j] = acc;
    }
}

// ---------------- weight pre-convert: [K][128] fp32 -> [128][K] bf16 hi/lo --
struct WSpecs {
    const float* src[16];
    int K[16];
    int off[16];
};
__global__ void wconv_kernel(WSpecs s, __nv_bfloat16* __restrict__ whi,
                             __nv_bfloat16* __restrict__ wlo)
{
    const float* W = s.src[blockIdx.x];
    int K = s.K[blockIdx.x];
    int off = s.off[blockIdx.x];
    int slab = blockIdx.y * 16;               // 16 n-values per y-block
    for (int idx = threadIdx.x; idx < K * 16; idx += blockDim.x) {
        int n = slab + idx / K;
        int k = idx % K;
        float x = W[(size_t)k * 128 + n];
        __nv_bfloat16 h = __float2bfloat16(x);
        float r = x - __bfloat162float(h);
        whi[off + (size_t)n * K + k] = h;
        wlo[off + (size_t)n * K + k] = __float2bfloat16(r);
    }
}

// ---------------- degree counting -------------------------------------------
__global__ void count_kernel(const int* __restrict__ dst, int n, float* __restrict__ cnt)
{
    int i = blockIdx.x * blockDim.x + threadIdx.x;
    if (i < n) atomicAdd(&cnt[dst[i]], 1.0f);
}
__global__ void inv_kernel(float* __restrict__ c, int n)
{
    int i = blockIdx.x * blockDim.x + threadIdx.x;
    if (i < n) c[i] = 1.0f / fmaxf(c[i], 1.0f);
}

// ---------------- warp-MMA bf16 split-2 GEMM --------------------------------
// C[:, colOff:+128] = [relu](A_concat @ W + bias); W pre-split bf16 [N=128][K].
// MODEA=0: A is [Nrows][K]. MODEA=1: A=[A | A2*scale2] (K=256, strides 128).
// DUAL=1: blockIdx.y picks (bOff0, col 0)/(bOff1, col 128), K=128.
// CTA 128x128 tile, 8 warps (4 M x 2 N), warp tile 32x64. K chunks of 64.
// acc += Ahi*Bhi + Ahi*Blo + Alo*Bhi  (lo*lo dropped, ~2^-18)
template<int MODEA, int DUAL>
__global__ __launch_bounds__(256)
void mma_gemm(const float* __restrict__ A, const float* __restrict__ A2,
              const float* __restrict__ scale2,
              const __nv_bfloat16* __restrict__ whi,
              const __nv_bfloat16* __restrict__ wlo,
              size_t bOff0, size_t bOff1,
              const float* __restrict__ bias, int relu,
              float* __restrict__ C, int ldc, int colOff,
              int Nrows, int K)
{
    extern __shared__ unsigned char dsm[];
    const int OFF_AH = 0, OFF_AL = 16384, OFF_BH = 32768, OFF_BL = 49152;
    int tid  = threadIdx.x;
    int wid  = tid >> 5, lane = tid & 31;
    int warpM = wid & 3, warpN = wid >> 2;       // 4 x 2 warp grid
    size_t bOff = bOff0;
    if (DUAL && blockIdx.y == 1) { bOff = bOff1; colOff += 128; }
    int brow = blockIdx.x * 128;

    // load-phase mapping: thread handles row lrow, half lhalf (32 elems)
    int lrow  = tid >> 1;
    int lhalf = tid & 1;
    int grow  = brow + lrow;
    bool rowok = grow < Nrows;
    float sc = 1.f;
    if (MODEA == 1) sc = rowok ? scale2[grow] : 0.f;

    float acc[16][4];
#pragma unroll
    for (int i = 0; i < 16; i++)
#pragma unroll
        for (int j = 0; j < 4; j++) acc[i][j] = 0.f;

    const int nch = K / 64;
    for (int c = 0; c < nch; c++) {
        if (c > 0) __syncthreads();   // protect smem from prior compute
        // ---- A chunk: 32 floats -> bf16 hi/lo, swizzled smem ----
        {
            const float* srcA;
            float mul = 1.f;
            int kbase = c * 64 + lhalf * 32;
            if (MODEA == 1) {
                if (kbase >= 128) { srcA = A2 + (size_t)grow * 128 + (kbase - 128); mul = sc; }
                else              { srcA = A  + (size_t)grow * 128 + kbase; }
            } else {
                srcA = A + (size_t)grow * K + kbase;
            }
#pragma unroll
            for (int g = 0; g < 4; g++) {      // 8 floats per group
                float4 a0 = make_float4(0.f, 0.f, 0.f, 0.f);
                float4 a1 = make_float4(0.f, 0.f, 0.f, 0.f);
                if (rowok) {
                    a0 = *reinterpret_cast<const float4*>(srcA + g * 8);
                    a1 = *reinterpret_cast<const float4*>(srcA + g * 8 + 4);
                }
                a0.x *= mul; a0.y *= mul; a0.z *= mul; a0.w *= mul;
                a1.x *= mul; a1.y *= mul; a1.z *= mul; a1.w *= mul;
                uint4 hi, lo;
                split2(a0.x, a0.y, hi.x, lo.x);
                split2(a0.z, a0.w, hi.y, lo.y);
                split2(a1.x, a1.y, hi.z, lo.z);
                split2(a1.z, a1.w, hi.w, lo.w);
                uint32_t so = SMEM_SWIZZLE_128B((uint32_t)(lrow * 128 + lhalf * 64 + g * 16));
                *reinterpret_cast<uint4*>(dsm + OFF_AH + so) = hi;
                *reinterpret_cast<uint4*>(dsm + OFF_AL + so) = lo;
            }
        }
        // ---- B chunk: pre-converted bf16, n = lrow ----
        {
            const uint4* bh = reinterpret_cast<const uint4*>(whi + bOff + (size_t)lrow * K + c * 64 + lhalf * 32);
            const uint4* bl = reinterpret_cast<const uint4*>(wlo + bOff + (size_t)lrow * K + c * 64 + lhalf * 32);
#pragma unroll
            for (int g = 0; g < 4; g++) {
                uint32_t so = SMEM_SWIZZLE_128B((uint32_t)(lrow * 128 + lhalf * 64 + g * 16));
                *reinterpret_cast<uint4*>(dsm + OFF_BH + so) = bh[g];
                *reinterpret_cast<uint4*>(dsm + OFF_BL + so) = bl[g];
            }
        }
        __syncthreads();
        // ---- compute: 4 k16 steps ----
#pragma unroll
        for (int k16 = 0; k16 < 4; k16++) {
            uint32_t ah[2][4], al[2][4];
#pragma unroll
            for (int tm = 0; tm < 2; tm++) {
                int r  = warpM * 32 + tm * 16 + (lane & 7) + ((lane >> 3) & 1) * 8;
                int cb = k16 * 32 + ((lane >> 4) & 1) * 16;
                uint32_t so = SMEM_SWIZZLE_128B((uint32_t)(r * 128 + cb));
                LDM4(ah[tm], smem_u32(dsm + OFF_AH + so));
                LDM4(al[tm], smem_u32(dsm + OFF_AL + so));
            }
            uint32_t bh[4][4], bl[4][4];
#pragma unroll
            for (int bq = 0; bq < 4; bq++) {
                int n  = warpN * 64 + bq * 16 + (lane & 7) + ((lane >> 4) & 1) * 8;
                int cb = k16 * 32 + ((lane >> 3) & 1) * 16;
                uint32_t so = SMEM_SWIZZLE_128B((uint32_t)(n * 128 + cb));
                LDM4(bh[bq], smem_u32(dsm + OFF_BH + so));
                LDM4(bl[bq], smem_u32(dsm + OFF_BL + so));
            }
#pragma unroll
            for (int tm = 0; tm < 2; tm++)
#pragma unroll
                for (int tn = 0; tn < 8; tn++) {
                    float* d = acc[tm * 8 + tn];
                    uint32_t* B  = &bh[tn >> 1][(tn & 1) * 2];
                    uint32_t* Bl = &bl[tn >> 1][(tn & 1) * 2];
                    MMA16816(d, ah[tm], B[0],  B[1]);
                    MMA16816(d, ah[tm], Bl[0], Bl[1]);
                    MMA16816(d, al[tm], B[0],  B[1]);
                }
        }
    }

    // ---- epilogue ----
#pragma unroll
    for (int tm = 0; tm < 2; tm++)
#pragma unroll
        for (int tn = 0; tn < 8; tn++) {
            float* d = acc[tm * 8 + tn];
            int r0  = brow + warpM * 32 + tm * 16 + (lane >> 2);
            int col = colOff + warpN * 64 + tn * 8 + (lane & 3) * 2;
            float b0 = 0.f, b1v = 0.f;
            if (bias) {
                float2 bb = *reinterpret_cast<const float2*>(bias + (col - colOff));
                b0 = bb.x; b1v = bb.y;
            }
            float o0 = d[0] + b0, o1 = d[1] + b1v;
            float o2 = d[2] + b0, o3 = d[3] + b1v;
            if (relu) {
                o0 = fmaxf(o0, 0.f); o1 = fmaxf(o1, 0.f);
                o2 = fmaxf(o2, 0.f); o3 = fmaxf(o3, 0.f);
            }
            if (r0 < Nrows)
                *reinterpret_cast<float2*>(C + (size_t)r0 * ldc + col) = make_float2(o0, o1);
            if (r0 + 8 < Nrows)
                *reinterpret_cast<float2*>(C + (size_t)(r0 + 8) * ldc + col) = make_float2(o2, o3);
        }
}

// ---------------- edge message + scatter-add (grid-stride) ------------------
template<int EDIM, bool SYM>
__global__ __launch_bounds__(256)
void edge_msg_kernel(const float* __restrict__ hshd,
                     const int* __restrict__ ei,
                     const float* __restrict__ ea, const float* __restrict__ eb,
                     const float* __restrict__ We, const float* __restrict__ bm,
                     float* __restrict__ aggr, int Etot, int Ehalf)
{
    __shared__ float Wes[EDIM * 128];
    __shared__ float bms[128];
    int tid = threadIdx.x;
    for (int i = tid; i < EDIM * 128; i += 256) Wes[i] = We[i];
    if (tid < 128) bms[tid] = bm[tid];
    __syncthreads();
    int wglob = blockIdx.x * 8 + (tid >> 5);
    int lane  = tid & 31;
    int step  = gridDim.x * 8;
    int c = lane << 2;
    for (int e = wglob; e < Etot; e += step) {
        int src, dst, eidx;
        if (SYM) {
            src = ei[e];
            if (e < Ehalf) { dst = ei[e + Ehalf]; eidx = e; }
            else           { dst = ei[e - Ehalf]; eidx = e - Ehalf; }
        } else {
            src = ei[e]; dst = ei[Etot + e]; eidx = e;
        }
        float aval = 0.f;
        if (SYM) {
            if (lane < 8)       aval = ea[(size_t)eidx * 8 + lane];
            else if (lane < 16) aval = eb[(size_t)eidx * 8 + (lane - 8)];
        } else {
            if (lane < EDIM)    aval = ea[(size_t)eidx * EDIM + lane];
        }
        float4 m = *reinterpret_cast<const float4*>(bms + c);
        float4 a = *reinterpret_cast<const float4*>(hshd + (size_t)src * 256 + c);
        float4 b = *reinterpret_cast<const float4*>(hshd + (size_t)dst * 256 + 128 + c);
        m.x += a.x + b.x; m.y += a.y + b.y; m.z += a.z + b.z; m.w += a.w + b.w;
#pragma unroll
        for (int k = 0; k < EDIM; k++) {
            float av = __shfl_sync(0xffffffffu, aval, k);
            float4 w = *reinterpret_cast<const float4*>(Wes + k * 128 + c);
            m.x = fmaf(av, w.x, m.x); m.y = fmaf(av, w.y, m.y);
            m.z = fmaf(av, w.z, m.z); m.w = fmaf(av, w.w, m.w);
        }
        m.x = fmaxf(m.x, 0.f); m.y = fmaxf(m.y, 0.f);
        m.z = fmaxf(m.z, 0.f); m.w = fmaxf(m.w, 0.f);
        red_add_v4(aggr + (size_t)dst * 128 + c, m);
    }
}

// ---------------- head: per coupling edge (grid-stride) ----------------------
__global__ __launch_bounds__(256)
void head_kernel(const float* __restrict__ g12, const int* __restrict__ ei3,
                 const float* __restrict__ ea3, const float* __restrict__ ea4,
                 const float* __restrict__ Wtail, const float* __restrict__ b1,
                 const float* __restrict__ W2, const float* __restrict__ b2,
                 float* __restrict__ out)
{
    __shared__ float Ws[16 * 128];
    __shared__ float b1s[128];
    __shared__ float W2s[128];
    int tid = threadIdx.x;
    for (int i = tid; i < 16 * 128; i += 256) Ws[i] = Wtail[i];
    if (tid < 128) { b1s[tid] = b1[tid]; W2s[tid] = W2[tid]; }
    __syncthreads();
    int wglob = blockIdx.x * 8 + (tid >> 5);
    int lane  = tid & 31;
    int step  = gridDim.x * 8;
    int c = lane << 2;
    for (int e = wglob; e < E3N; e += step) {
        int s = ei3[e], d = ei3[E3N + e];
        float aval = 0.f;
        if (lane < 8)       aval = ea3[(size_t)e * 8 + lane];
        else if (lane < 16) aval = ea4[(size_t)e * 8 + (lane - 8)];
        float4 v = *reinterpret_cast<const float4*>(b1s + c);
        float4 a = *reinterpret_cast<const float4*>(g12 + (size_t)s * 256 + c);
        float4 b = *reinterpret_cast<const float4*>(g12 + (size_t)d * 256 + 128 + c);
        v.x += a.x + b.x; v.y += a.y + b.y; v.z += a.z + b.z; v.w += a.w + b.w;
#pragma unroll
        for (int k = 0; k < 16; k++) {
            float av = __shfl_sync(0xffffffffu, aval, k);
            float4 w = *reinterpret_cast<const float4*>(Ws + k * 128 + c);
            v.x = fmaf(av, w.x, v.x); v.y = fmaf(av, w.y, v.y);
            v.z = fmaf(av, w.z, v.z); v.w = fmaf(av, w.w, v.w);
        }
        v.x = fmaxf(v.x, 0.f); v.y = fmaxf(v.y, 0.f);
        v.z = fmaxf(v.z, 0.f); v.w = fmaxf(v.w, 0.f);
        float4 w2 = *reinterpret_cast<const float4*>(W2s + c);
        float p = v.x * w2.x + v.y * w2.y + v.z * w2.z + v.w * w2.w;
#pragma unroll
        for (int o = 16; o > 0; o >>= 1) p += __shfl_xor_sync(0xffffffffu, p, o);
        if (lane == 0) out[e] = p + b2[0];
    }
}

// ---------------- host orchestration ----------------------------------------
extern "C" void kernel_launch(void* const* d_in, const int* in_sizes, int n_in,
                              void* d_out, int out_size)
{
    const float* x      = (const float*)d_in[0];
    const int*   ei     = (const int*)  d_in[1];
    const float* eattr  = (const float*)d_in[2];
    const int*   ei3    = (const int*)  d_in[3];
    const float* ea3    = (const float*)d_in[4];
    const float* ea4    = (const float*)d_in[5];
    const float* bn1g   = (const float*)d_in[6];
    const float* bn1b   = (const float*)d_in[7];
    const float* lin1W  = (const float*)d_in[8];
    const float* lin1b  = (const float*)d_in[9];
    const float* bn2g   = (const float*)d_in[10];
    const float* bn2b   = (const float*)d_in[11];
    const float* lin2W  = (const float*)d_in[12];
    const float* lin2b  = (const float*)d_in[13];
    const float* c1Ws   = (const float*)d_in[14];
    const float* c1Wd   = (const float*)d_in[15];
    const float* c1We   = (const float*)d_in[16];
    const float* c1bm   = (const float*)d_in[17];
    const float* c1Wu   = (const float*)d_in[18];
    const float* c1bu   = (const float*)d_in[19];
    const float* c2Ws   = (const float*)d_in[20];
    const float* c2Wd   = (const float*)d_in[21];
    const float* c2We   = (const float*)d_in[22];
    const float* c2bm   = (const float*)d_in[23];
    const float* c2Wu   = (const float*)d_in[24];
    const float* c2bu   = (const float*)d_in[25];
    const float* headW1 = (const float*)d_in[26];
    const float* headb1 = (const float*)d_in[27];
    const float* headW2 = (const float*)d_in[28];
    const float* headb2 = (const float*)d_in[29];
    float* out = (float*)d_out;

    float *h1, *hA, *hB, *hshd, *aggr, *inv1, *inv2, *st1, *st2, *W2f, *b2f;
    __nv_bfloat16 *whi, *wlo;
    cudaGetSymbolAddress((void**)&h1,   g_h1);
    cudaGetSymbolAddress((void**)&hA,   g_hA);
    cudaGetSymbolAddress((void**)&hB,   g_hB);
    cudaGetSymbolAddress((void**)&hshd, g_hshd);
    cudaGetSymbolAddress((void**)&aggr, g_aggr);
    cudaGetSymbolAddress((void**)&inv1, g_inv1);
    cudaGetSymbolAddress((void**)&inv2, g_inv2);
    cudaGetSymbolAddress((void**)&st1,  g_stat1);
    cudaGetSymbolAddress((void**)&st2,  g_stat2);
    cudaGetSymbolAddress((void**)&W2f,  g_W2f);
    cudaGetSymbolAddress((void**)&b2f,  g_b2f);
    cudaGetSymbolAddress((void**)&whi,  g_whi);
    cudaGetSymbolAddress((void**)&wlo,  g_wlo);

    const int GB = (NN + 127) / 128;
    const dim3 G1(GB, 1), G2(GB, 2);
    const int EGRID = 1184;
    const int MM_SMEM = 65536;
    cudaFuncSetAttribute(mma_gemm<0, 0>, cudaFuncAttributeMaxDynamicSharedMemorySize, MM_SMEM);
    cudaFuncSetAttribute(mma_gemm<0, 1>, cudaFuncAttributeMaxDynamicSharedMemorySize, MM_SMEM);
    cudaFuncSetAttribute(mma_gemm<1, 0>, cudaFuncAttributeMaxDynamicSharedMemorySize, MM_SMEM);

    // weight offsets in g_whi/g_wlo ([N=128][K] layout)
    const int OFF_W2F  = 0;
    const int OFF_C1S  = 32768,  OFF_C1D = 81920,  OFF_C1U = 131072;
    const int OFF_C2S  = 229376, OFF_C2D = 278528, OFF_C2U = 327680;
    const int OFF_HA   = 425984, OFF_HB  = 442368;

    WSpecs ws;
    ws.src[0] = W2f;  ws.K[0] = 256; ws.off[0] = OFF_W2F;
    for (int l = 0; l < 3; l++) {
        ws.src[1 + l]  = c1Ws + l * 16384; ws.K[1 + l]  = 128; ws.off[1 + l]  = OFF_C1S + l * 16384;
        ws.src[4 + l]  = c1Wd + l * 16384; ws.K[4 + l]  = 128; ws.off[4 + l]  = OFF_C1D + l * 16384;
        ws.src[7 + l]  = c1Wu + l * 32768; ws.K[7 + l]  = 256; ws.off[7 + l]  = OFF_C1U + l * 32768;
        ws.src[10 + l] = c2Ws + l * 16384; ws.K[10 + l] = 128; ws.off[10 + l] = OFF_C2S + l * 16384;
    }
    ws.src[13] = headW1;         ws.K[13] = 128; ws.off[13] = OFF_HA;
    ws.src[14] = headW1 + 16384; ws.K[14] = 128; ws.off[14] = OFF_HB;
    WSpecs ws2;
    for (int l = 0; l < 3; l++) {
        ws2.src[l]     = c2Wd + l * 16384; ws2.K[l]     = 128; ws2.off[l]     = OFF_C2D + l * 16384;
        ws2.src[3 + l] = c2Wu + l * 32768; ws2.K[3 + l] = 256; ws2.off[3 + l] = OFF_C2U + l * 32768;
    }

    // -------- lin_node (slot 7 incl. memsets = mma_gemm lin2 for ncu) -------
    cudaMemsetAsync(st1, 0, 32 * sizeof(float));                              // 1
    stats13_kernel<<<592, 256>>>(x, st1);                                     // 2
    cudaMemsetAsync(st2, 0, 2 * DIMF * sizeof(float));                        // 3
    h1_kernel<<<(NN + H1_ROWS - 1) / H1_ROWS, 256>>>(x, st1, bn1g, bn1b,
                                                     lin1W, lin1b, h1, st2);  // 4
    fold2_kernel<<<DIMF, DIM>>>(st2, bn2g, bn2b, lin2W, lin2b, W2f, b2f);     // 5
    wconv_kernel<<<dim3(15, 8), 256>>>(ws, whi, wlo);                         // 6
    mma_gemm<0, 0><<<G1, 256, MM_SMEM>>>(h1, nullptr, nullptr, whi, wlo,
                                         OFF_W2F, 0, b2f, 1, hA, 128, 0, NN, 256); // 7
    wconv_kernel<<<dim3(6, 8), 256>>>(ws2, whi, wlo);

    // -------- degree counts --------
    cudaMemsetAsync(inv1, 0, NN * sizeof(float));
    cudaMemsetAsync(inv2, 0, NN * sizeof(float));
    count_kernel<<<(EE + 255) / 256, 256>>>(ei + EE, EE, inv1);
    count_kernel<<<(E3N + 255) / 256, 256>>>(ei3 + E3N, E3N, inv2);
    count_kernel<<<(E3N + 255) / 256, 256>>>(ei3, E3N, inv2);
    inv_kernel<<<(NN + 255) / 256, 256>>>(inv1, NN);
    inv_kernel<<<(NN + 255) / 256, 256>>>(inv2, NN);

    float* cur = hA;
    float* nxt = hB;

    // -------- conv1 x3 --------
    for (int l = 0; l < 3; l++) {
        mma_gemm<0, 1><<<G2, 256, MM_SMEM>>>(cur, nullptr, nullptr, whi, wlo,
                                             OFF_C1S + l * 16384, OFF_C1D + l * 16384,
                                             nullptr, 0, hshd, 256, 0, NN, 128);
        cudaMemsetAsync(aggr, 0, (size_t)NN * 128 * sizeof(float));
        edge_msg_kernel<8, false><<<EGRID, 256>>>(hshd, ei, eattr, nullptr,
                                                  c1We + l * 8 * 128, c1bm + l * 128,
                                                  aggr, EE, 0);
        mma_gemm<1, 0><<<G1, 256, MM_SMEM>>>(cur, aggr, inv1, whi, wlo,
                                             OFF_C1U + l * 32768, 0,
                                             c1bu + l * 128, 1, nxt, 128, 0, NN, 256);
        float* t = cur; cur = nxt; nxt = t;
    }

    // -------- conv2 x3 --------
    for (int l = 0; l < 3; l++) {
        mma_gemm<0, 1><<<G2, 256, MM_SMEM>>>(cur, nullptr, nullptr, whi, wlo,
                                             OFF_C2S + l * 16384, OFF_C2D + l * 16384,
                                             nullptr, 0, hshd, 256, 0, NN, 128);
        cudaMemsetAsync(aggr, 0, (size_t)NN * 128 * sizeof(float));
        edge_msg_kernel<16, true><<<EGRID, 256>>>(hshd, ei3, ea3, ea4,
                                                  c2We + l * 16 * 128, c2bm + l * 128,
                                                  aggr, 2 * E3N, E3N);
        mma_gemm<1, 0><<<G1, 256, MM_SMEM>>>(cur, aggr, inv2, whi, wlo,
                                             OFF_C2U + l * 32768, 0,
                                             c2bu + l * 128, 1, nxt, 128, 0, NN, 256);
        float* t = cur; cur = nxt; nxt = t;
    }

    // -------- head --------
    mma_gemm<0, 1><<<G2, 256, MM_SMEM>>>(cur, nullptr, nullptr, whi, wlo,
                                         OFF_HA, OFF_HB,
                                         nullptr, 0, hshd, 256, 0, NN, 128);
    head_kernel<<<EGRID, 256>>>(hshd, ei3, ea3, ea4,
                                headW1 + 256 * 128, headb1, headW2, headb2, out);
}

// round 12
// speedup vs baseline: 1.3176x; 1.0290x over previous
#include <cuda_runtime.h>
#include <cuda_bf16.h>
#include <cstdint>

#define NN      100000
#define EE      800000
#define E3N     400000
#define NODE_IN 13
#define DIM     128
#define DIMF    256

// ---------------- scratch (static __device__; no allocation allowed) -------
__device__ float g_hshd[(size_t)NN * DIMF];
__device__ float g_aggr[(size_t)NN * DIM];
__device__ float g_inv1[NN];
__device__ float g_inv2[NN];
__device__ float g_stat1[32];
__device__ float g_stat2[2 * DIMF];
__device__ float g_b2f[DIM];
// activations, bf16 hi/lo split, [row][256] (padded rows for tail blocks)
__device__ __nv_bfloat16 g_ahi[(size_t)(NN + 128) * DIMF];
__device__ __nv_bfloat16 g_alo[(size_t)(NN + 128) * DIMF];
// pre-converted weights, transposed [N=128][K] bf16, hi/lo split
#define WTOT 458752
__device__ __nv_bfloat16 g_whi[WTOT];
__device__ __nv_bfloat16 g_wlo[WTOT];

// ---------------- small helpers ---------------------------------------------
__device__ __forceinline__ unsigned smem_u32(const void* p)
{
    return (unsigned)__cvta_generic_to_shared(p);
}
__device__ __forceinline__ void red_add_v4(float* p, float4 v)
{
    asm volatile("red.global.add.v4.f32 [%0], {%1, %2, %3, %4};"
                 :: "l"(p), "f"(v.x), "f"(v.y), "f"(v.z), "f"(v.w) : "memory");
}

#define SMEM_SWIZZLE_128B(o) ((o) ^ (((o) >> 3) & 0x70))

// split x,y -> hi/lo bf16x2 packed
__device__ __forceinline__ void split2(float x, float y, uint32_t& hi, uint32_t& lo)
{
    __nv_bfloat16 hx = __float2bfloat16(x), hy = __float2bfloat16(y);
    float rx = x - __bfloat162float(hx);
    float ry = y - __bfloat162float(hy);
    __nv_bfloat16 lx = __float2bfloat16(rx), ly = __float2bfloat16(ry);
    hi = (uint32_t)__bfloat16_as_ushort(hx) | ((uint32_t)__bfloat16_as_ushort(hy) << 16);
    lo = (uint32_t)__bfloat16_as_ushort(lx) | ((uint32_t)__bfloat16_as_ushort(ly) << 16);
}
__device__ __forceinline__ void split1(float x, __nv_bfloat16& h, __nv_bfloat16& l)
{
    h = __float2bfloat16(x);
    l = __float2bfloat16(x - __bfloat162float(h));
}

#define LDM4(r, addr) \
    asm volatile("ldmatrix.sync.aligned.m8n8.x4.shared.b16 {%0,%1,%2,%3}, [%4];" \
                 : "=r"((r)[0]), "=r"((r)[1]), "=r"((r)[2]), "=r"((r)[3]) : "r"(addr))

#define MMA16816(d, a, b0, b1) \
    asm volatile("mma.sync.aligned.m16n8k16.row.col.f32.bf16.bf16.f32 " \
                 "{%0,%1,%2,%3}, {%4,%5,%6,%7}, {%8,%9}, {%0,%1,%2,%3};" \
                 : "+f"((d)[0]), "+f"((d)[1]), "+f"((d)[2]), "+f"((d)[3]) \
                 : "r"((a)[0]), "r"((a)[1]), "r"((a)[2]), "r"((a)[3]), \
                   "r"(b0), "r"(b1))

// ---------------- column stats of x (13 cols) ------------------------------
__global__ void stats13_kernel(const float* __restrict__ x, float* __restrict__ stat)
{
    float ls[NODE_IN], lq[NODE_IN];
#pragma unroll
    for (int c = 0; c < NODE_IN; c++) { ls[c] = 0.f; lq[c] = 0.f; }
    int stride = gridDim.x * blockDim.x;
    for (int r = blockIdx.x * blockDim.x + threadIdx.x; r < NN; r += stride) {
#pragma unroll
        for (int c = 0; c < NODE_IN; c++) {
            float v = x[(size_t)r * NODE_IN + c];
            ls[c] += v; lq[c] += v * v;
        }
    }
    __shared__ float ss[2 * NODE_IN];
    if (threadIdx.x < 2 * NODE_IN) ss[threadIdx.x] = 0.f;
    __syncthreads();
#pragma unroll
    for (int c = 0; c < NODE_IN; c++) {
        atomicAdd(&ss[c], ls[c]);
        atomicAdd(&ss[NODE_IN + c], lq[c]);
    }
    __syncthreads();
    if (threadIdx.x < 2 * NODE_IN) atomicAdd(&stat[threadIdx.x], ss[threadIdx.x]);
}

// ------- h1 = relu(bn1(x)@W1+b1) -> bf16 hi/lo directly (cols 0..255) -------
#define H1_ROWS 64
__global__ __launch_bounds__(256)
void h1_kernel(const float* __restrict__ x, const float* __restrict__ stat,
               const float* __restrict__ bn1g, const float* __restrict__ bn1b,
               const float* __restrict__ W1, const float* __restrict__ b1,
               __nv_bfloat16* __restrict__ ahi, __nv_bfloat16* __restrict__ alo,
               float* __restrict__ stat2)
{
    __shared__ float xs[H1_ROWS * NODE_IN];
    int t = threadIdx.x;
    float w[NODE_IN];
    float bb = b1[t];
#pragma unroll
    for (int k = 0; k < NODE_IN; k++) {
        float m = stat[k] * (1.0f / NN);
        float v = stat[NODE_IN + k] * (1.0f / NN) - m * m;
        float a = bn1g[k] * rsqrtf(v + 1e-5f);
        float be = bn1b[k] - m * a;
        float wv = W1[k * DIMF + t];
        w[k] = a * wv;
        bb += be * wv;
    }
    int r0 = blockIdx.x * H1_ROWS;
    int nr = min(H1_ROWS, NN - r0);
    for (int i = t; i < nr * NODE_IN; i += 256)
        xs[i] = x[(size_t)r0 * NODE_IN + i];
    __syncthreads();
    float s = 0.f, q = 0.f;
    for (int r = 0; r < nr; r++) {
        float acc = bb;
#pragma unroll
        for (int k = 0; k < NODE_IN; k++) acc = fmaf(xs[r * NODE_IN + k], w[k], acc);
        acc = fmaxf(acc, 0.f);
        __nv_bfloat16 h, l;
        split1(acc, h, l);
        ahi[(size_t)(r0 + r) * DIMF + t] = h;
        alo[(size_t)(r0 + r) * DIMF + t] = l;
        s += acc; q += acc * acc;
    }
    atomicAdd(&stat2[t], s);
    atomicAdd(&stat2[DIMF + t], q);
}

// -------- fold bn2 into lin2, emit transposed bf16 hi/lo + bias --------------
__global__ void fold2w_kernel(const float* __restrict__ stat2,
                              const float* __restrict__ g, const float* __restrict__ b,
                              const float* __restrict__ W2, const float* __restrict__ b2,
                              __nv_bfloat16* __restrict__ whi, __nv_bfloat16* __restrict__ wlo,
                              float* __restrict__ b2f)
{
    int k = blockIdx.x;   // 0..255 input channel
    int j = threadIdx.x;  // 0..127 output channel
    __shared__ float al;
    if (j == 0) {
        float m = stat2[k] * (1.0f / NN);
        float v = stat2[DIMF + k] * (1.0f / NN) - m * m;
        al = g[k] * rsqrtf(v + 1e-5f);
    }
    __syncthreads();
    float wv = al * W2[k * DIM + j];
    __nv_bfloat16 h, l;
    split1(wv, h, l);
    whi[(size_t)j * 256 + k] = h;   // OFF_W2F = 0, [n=j][k], K=256
    wlo[(size_t)j * 256 + k] = l;
    if (k == 0) {
        float acc = b2[j];
        for (int kk = 0; kk < DIMF; kk++) {
            float m = stat2[kk] * (1.0f / NN);
            float v = stat2[DIMF + kk] * (1.0f / NN) - m * m;
            float a = g[kk] * rsqrtf(v + 1e-5f);
            float be = b[kk] - m * a;
            acc += be * W2[kk * DIM + j];
        }
        b2f[j] = acc;
    }
}

// ---------------- weight pre-convert: [K][128] fp32 -> [128][K] bf16 hi/lo --
struct WSpecs {
    const float* src[16];
    int K[16];
    int off[16];
};
__global__ void wconv_kernel(WSpecs s, __nv_bfloat16* __restrict__ whi,
                             __nv_bfloat16* __restrict__ wlo)
{
    const float* W = s.src[blockIdx.x];
    int K = s.K[blockIdx.x];
    int off = s.off[blockIdx.x];
    int slab = blockIdx.y * 16;
    for (int idx = threadIdx.x; idx < K * 16; idx += blockDim.x) {
        int n = slab + idx / K;
        int k = idx % K;
        float x = W[(size_t)k * 128 + n];
        __nv_bfloat16 h, l;
        split1(x, h, l);
        whi[off + (size_t)n * K + k] = h;
        wlo[off + (size_t)n * K + k] = l;
    }
}

// ---- aconv: aggr[row][128] * inv[row] -> ahi/alo cols 128..255 --------------
__global__ __launch_bounds__(256)
void aconv_kernel(const float* __restrict__ src, const float* __restrict__ scale,
                  __nv_bfloat16* __restrict__ ahi, __nv_bfloat16* __restrict__ alo)
{
    int idx = blockIdx.x * 256 + threadIdx.x;      // 8 elems per thread
    int row = idx >> 4;
    int g   = idx & 15;
    if (row >= NN) return;
    float s = scale[row];
    const float4* p = reinterpret_cast<const float4*>(src + (size_t)row * 128 + g * 8);
    float4 a0 = p[0], a1 = p[1];
    a0.x *= s; a0.y *= s; a0.z *= s; a0.w *= s;
    a1.x *= s; a1.y *= s; a1.z *= s; a1.w *= s;
    uint4 hi, lo;
    split2(a0.x, a0.y, hi.x, lo.x);
    split2(a0.z, a0.w, hi.y, lo.y);
    split2(a1.x, a1.y, hi.z, lo.z);
    split2(a1.z, a1.w, hi.w, lo.w);
    size_t o = (size_t)row * 256 + 128 + g * 8;
    *reinterpret_cast<uint4*>(ahi + o) = hi;
    *reinterpret_cast<uint4*>(alo + o) = lo;
}

// ---------------- degree counting -------------------------------------------
__global__ void count_kernel(const int* __restrict__ dst, int n, float* __restrict__ cnt)
{
    int i = blockIdx.x * blockDim.x + threadIdx.x;
    if (i < n) atomicAdd(&cnt[dst[i]], 1.0f);
}
__global__ void inv_kernel(float* __restrict__ c, int n)
{
    int i = blockIdx.x * blockDim.x + threadIdx.x;
    if (i < n) c[i] = 1.0f / fmaxf(c[i], 1.0f);
}

// ---------------- warp-MMA bf16 split-2 GEMM --------------------------------
// A: bf16 hi/lo [row][256] (cols 0..K-1). W: pre-split bf16 [N=128][K].
// DUAL=1: blockIdx.y picks (bOff0, col 0)/(bOff1, col 128); K=128.
// OUTW=0: write fp32 C[:, colOff:+128]. OUTW=1: write bf16 hi/lo cols 0..127
//         of ohi/olo in place (safe: each CTA writes only rows it reads).
// CTA 128x128 tile, 8 warps (4M x 2N), warp tile 32x64, K chunks of 64.
// acc += Ahi*Bhi + Ahi*Blo + Alo*Bhi
template<int DUAL, int OUTW>
__global__ __launch_bounds__(256)
void mma_gemm(const __nv_bfloat16* __restrict__ ahi,
              const __nv_bfloat16* __restrict__ alo,
              const __nv_bfloat16* __restrict__ whi,
              const __nv_bfloat16* __restrict__ wlo,
              size_t bOff0, size_t bOff1,
              const float* __restrict__ bias, int relu,
              float* __restrict__ C, int ldc, int colOff,
              __nv_bfloat16* __restrict__ ohi, __nv_bfloat16* __restrict__ olo,
              int Nrows, int K)
{
    extern __shared__ unsigned char dsm[];
    const int OFF_AH = 0, OFF_AL = 16384, OFF_BH = 32768, OFF_BL = 49152;
    int tid  = threadIdx.x;
    int wid  = tid >> 5, lane = tid & 31;
    int warpM = wid & 3, warpN = wid >> 2;
    size_t bOff = bOff0;
    if (DUAL && blockIdx.y == 1) { bOff = bOff1; colOff += 128; }
    int brow = blockIdx.x * 128;

    int lrow  = tid >> 1;
    int lhalf = tid & 1;
    int grow  = brow + lrow;   // may exceed Nrows; buffer padded, outputs guarded

    float acc[16][4];
#pragma unroll
    for (int i = 0; i < 16; i++)
#pragma unroll
        for (int j = 0; j < 4; j++) acc[i][j] = 0.f;

    const int nch = K / 64;
    for (int c = 0; c < nch; c++) {
        if (c > 0) __syncthreads();
        // ---- A chunk: pure bf16 copy, swizzled ----
        {
            const uint4* ph = reinterpret_cast<const uint4*>(ahi + (size_t)grow * 256 + c * 64 + lhalf * 32);
            const uint4* pl = reinterpret_cast<const uint4*>(alo + (size_t)grow * 256 + c * 64 + lhalf * 32);
#pragma unroll
            for (int g = 0; g < 4; g++) {
                uint32_t so = SMEM_SWIZZLE_128B((uint32_t)(lrow * 128 + lhalf * 64 + g * 16));
                *reinterpret_cast<uint4*>(dsm + OFF_AH + so) = ph[g];
                *reinterpret_cast<uint4*>(dsm + OFF_AL + so) = pl[g];
            }
        }
        // ---- B chunk ----
        {
            const uint4* bh = reinterpret_cast<const uint4*>(whi + bOff + (size_t)lrow * K + c * 64 + lhalf * 32);
            const uint4* bl = reinterpret_cast<const uint4*>(wlo + bOff + (size_t)lrow * K + c * 64 + lhalf * 32);
#pragma unroll
            for (int g = 0; g < 4; g++) {
                uint32_t so = SMEM_SWIZZLE_128B((uint32_t)(lrow * 128 + lhalf * 64 + g * 16));
                *reinterpret_cast<uint4*>(dsm + OFF_BH + so) = bh[g];
                *reinterpret_cast<uint4*>(dsm + OFF_BL + so) = bl[g];
            }
        }
        __syncthreads();
        // ---- compute: 4 k16 steps ----
#pragma unroll
        for (int k16 = 0; k16 < 4; k16++) {
            uint32_t ah[2][4], al[2][4];
#pragma unroll
            for (int tm = 0; tm < 2; tm++) {
                int r  = warpM * 32 + tm * 16 + (lane & 7) + ((lane >> 3) & 1) * 8;
                int cb = k16 * 32 + ((lane >> 4) & 1) * 16;
                uint32_t so = SMEM_SWIZZLE_128B((uint32_t)(r * 128 + cb));
                LDM4(ah[tm], smem_u32(dsm + OFF_AH + so));
                LDM4(al[tm], smem_u32(dsm + OFF_AL + so));
            }
            uint32_t bh[4][4], bl[4][4];
#pragma unroll
            for (int bq = 0; bq < 4; bq++) {
                int n  = warpN * 64 + bq * 16 + (lane & 7) + ((lane >> 4) & 1) * 8;
                int cb = k16 * 32 + ((lane >> 3) & 1) * 16;
                uint32_t so = SMEM_SWIZZLE_128B((uint32_t)(n * 128 + cb));
                LDM4(bh[bq], smem_u32(dsm + OFF_BH + so));
                LDM4(bl[bq], smem_u32(dsm + OFF_BL + so));
            }
#pragma unroll
            for (int tm = 0; tm < 2; tm++)
#pragma unroll
                for (int tn = 0; tn < 8; tn++) {
                    float* d = acc[tm * 8 + tn];
                    uint32_t* B  = &bh[tn >> 1][(tn & 1) * 2];
                    uint32_t* Bl = &bl[tn >> 1][(tn & 1) * 2];
                    MMA16816(d, ah[tm], B[0],  B[1]);
                    MMA16816(d, ah[tm], Bl[0], Bl[1]);
                    MMA16816(d, al[tm], B[0],  B[1]);
                }
        }
    }

    // ---- epilogue ----
#pragma unroll
    for (int tm = 0; tm < 2; tm++)
#pragma unroll
        for (int tn = 0; tn < 8; tn++) {
            float* d = acc[tm * 8 + tn];
            int r0   = brow + warpM * 32 + tm * 16 + (lane >> 2);
            int colL = warpN * 64 + tn * 8 + (lane & 3) * 2;   // 0..127 local
            float b0 = 0.f, b1v = 0.f;
            if (bias) {
                float2 bb = *reinterpret_cast<const float2*>(bias + colL);
                b0 = bb.x; b1v = bb.y;
            }
            float o0 = d[0] + b0, o1 = d[1] + b1v;
            float o2 = d[2] + b0, o3 = d[3] + b1v;
            if (relu) {
                o0 = fmaxf(o0, 0.f); o1 = fmaxf(o1, 0.f);
                o2 = fmaxf(o2, 0.f); o3 = fmaxf(o3, 0.f);
            }
            if (OUTW == 0) {
                int col = colOff + colL;
                if (r0 < Nrows)
                    *reinterpret_cast<float2*>(C + (size_t)r0 * ldc + col) = make_float2(o0, o1);
                if (r0 + 8 < Nrows)
                    *reinterpret_cast<float2*>(C + (size_t)(r0 + 8) * ldc + col) = make_float2(o2, o3);
            } else {
                uint32_t h01, l01, h23, l23;
                split2(o0, o1, h01, l01);
                split2(o2, o3, h23, l23);
                if (r0 < Nrows) {
                    *reinterpret_cast<uint32_t*>(ohi + (size_t)r0 * 256 + colL) = h01;
                    *reinterpret_cast<uint32_t*>(olo + (size_t)r0 * 256 + colL) = l01;
                }
                if (r0 + 8 < Nrows) {
                    *reinterpret_cast<uint32_t*>(ohi + (size_t)(r0 + 8) * 256 + colL) = h23;
                    *reinterpret_cast<uint32_t*>(olo + (size_t)(r0 + 8) * 256 + colL) = l23;
                }
            }
        }
}

// ---------------- edge message + scatter-add (grid-stride) ------------------
template<int EDIM, bool SYM>
__global__ __launch_bounds__(256)
void edge_msg_kernel(const float* __restrict__ hshd,
                     const int* __restrict__ ei,
                     const float* __restrict__ ea, const float* __restrict__ eb,
                     const float* __restrict__ We, const float* __restrict__ bm,
                     float* __restrict__ aggr, int Etot, int Ehalf)
{
    __shared__ float Wes[EDIM * 128];
    __shared__ float bms[128];
    int tid = threadIdx.x;
    for (int i = tid; i < EDIM * 128; i += 256) Wes[i] = We[i];
    if (tid < 128) bms[tid] = bm[tid];
    __syncthreads();
    int wglob = blockIdx.x * 8 + (tid >> 5);
    int lane  = tid & 31;
    int step  = gridDim.x * 8;
    int c = lane << 2;
    for (int e = wglob; e < Etot; e += step) {
        int src, dst, eidx;
        if (SYM) {
            src = ei[e];
            if (e < Ehalf) { dst = ei[e + Ehalf]; eidx = e; }
            else           { dst = ei[e - Ehalf]; eidx = e - Ehalf; }
        } else {
            src = ei[e]; dst = ei[Etot + e]; eidx = e;
        }
        float aval = 0.f;
        if (SYM) {
            if (lane < 8)       aval = ea[(size_t)eidx * 8 + lane];
            else if (lane < 16) aval = eb[(size_t)eidx * 8 + (lane - 8)];
        } else {
            if (lane < EDIM)    aval = ea[(size_t)eidx * EDIM + lane];
        }
        float4 m = *reinterpret_cast<const float4*>(bms + c);
        float4 a = *reinterpret_cast<const float4*>(hshd + (size_t)src * 256 + c);
        float4 b = *reinterpret_cast<const float4*>(hshd + (size_t)dst * 256 + 128 + c);
        m.x += a.x + b.x; m.y += a.y + b.y; m.z += a.z + b.z; m.w += a.w + b.w;
#pragma unroll
        for (int k = 0; k < EDIM; k++) {
            float av = __shfl_sync(0xffffffffu, aval, k);
            float4 w = *reinterpret_cast<const float4*>(Wes + k * 128 + c);
            m.x = fmaf(av, w.x, m.x); m.y = fmaf(av, w.y, m.y);
            m.z = fmaf(av, w.z, m.z); m.w = fmaf(av, w.w, m.w);
        }
        m.x = fmaxf(m.x, 0.f); m.y = fmaxf(m.y, 0.f);
        m.z = fmaxf(m.z, 0.f); m.w = fmaxf(m.w, 0.f);
        red_add_v4(aggr + (size_t)dst * 128 + c, m);
    }
}

// ---------------- head: per coupling edge (grid-stride) ----------------------
__global__ __launch_bounds__(256)
void head_kernel(const float* __restrict__ g12, const int* __restrict__ ei3,
                 const float* __restrict__ ea3, const float* __restrict__ ea4,
                 const float* __restrict__ Wtail, const float* __restrict__ b1,
                 const float* __restrict__ W2, const float* __restrict__ b2,
                 float* __restrict__ out)
{
    __shared__ float Ws[16 * 128];
    __shared__ float b1s[128];
    __shared__ float W2s[128];
    int tid = threadIdx.x;
    for (int i = tid; i < 16 * 128; i += 256) Ws[i] = Wtail[i];
    if (tid < 128) { b1s[tid] = b1[tid]; W2s[tid] = W2[tid]; }
    __syncthreads();
    int wglob = blockIdx.x * 8 + (tid >> 5);
    int lane  = tid & 31;
    int step  = gridDim.x * 8;
    int c = lane << 2;
    for (int e = wglob; e < E3N; e += step) {
        int s = ei3[e], d = ei3[E3N + e];
        float aval = 0.f;
        if (lane < 8)       aval = ea3[(size_t)e * 8 + lane];
        else if (lane < 16) aval = ea4[(size_t)e * 8 + (lane - 8)];
        float4 v = *reinterpret_cast<const float4*>(b1s + c);
        float4 a = *reinterpret_cast<const float4*>(g12 + (size_t)s * 256 + c);
        float4 b = *reinterpret_cast<const float4*>(g12 + (size_t)d * 256 + 128 + c);
        v.x += a.x + b.x; v.y += a.y + b.y; v.z += a.z + b.z; v.w += a.w + b.w;
#pragma unroll
        for (int k = 0; k < 16; k++) {
            float av = __shfl_sync(0xffffffffu, aval, k);
            float4 w = *reinterpret_cast<const float4*>(Ws + k * 128 + c);
            v.x = fmaf(av, w.x, v.x); v.y = fmaf(av, w.y, v.y);
            v.z = fmaf(av, w.z, v.z); v.w = fmaf(av, w.w, v.w);
        }
        v.x = fmaxf(v.x, 0.f); v.y = fmaxf(v.y, 0.f);
        v.z = fmaxf(v.z, 0.f); v.w = fmaxf(v.w, 0.f);
        float4 w2 = *reinterpret_cast<const float4*>(W2s + c);
        float p = v.x * w2.x + v.y * w2.y + v.z * w2.z + v.w * w2.w;
#pragma unroll
        for (int o = 16; o > 0; o >>= 1) p += __shfl_xor_sync(0xffffffffu, p, o);
        if (lane == 0) out[e] = p + b2[0];
    }
}

// ---------------- host orchestration ----------------------------------------
extern "C" void kernel_launch(void* const* d_in, const int* in_sizes, int n_in,
                              void* d_out, int out_size)
{
    const float* x      = (const float*)d_in[0];
    const int*   ei     = (const int*)  d_in[1];
    const float* eattr  = (const float*)d_in[2];
    const int*   ei3    = (const int*)  d_in[3];
    const float* ea3    = (const float*)d_in[4];
    const float* ea4    = (const float*)d_in[5];
    const float* bn1g   = (const float*)d_in[6];
    const float* bn1b   = (const float*)d_in[7];
    const float* lin1W  = (const float*)d_in[8];
    const float* lin1b  = (const float*)d_in[9];
    const float* bn2g   = (const float*)d_in[10];
    const float* bn2b   = (const float*)d_in[11];
    const float* lin2W  = (const float*)d_in[12];
    const float* lin2b  = (const float*)d_in[13];
    const float* c1Ws   = (const float*)d_in[14];
    const float* c1Wd   = (const float*)d_in[15];
    const float* c1We   = (const float*)d_in[16];
    const float* c1bm   = (const float*)d_in[17];
    const float* c1Wu   = (const float*)d_in[18];
    const float* c1bu   = (const float*)d_in[19];
    const float* c2Ws   = (const float*)d_in[20];
    const float* c2Wd   = (const float*)d_in[21];
    const float* c2We   = (const float*)d_in[22];
    const float* c2bm   = (const float*)d_in[23];
    const float* c2Wu   = (const float*)d_in[24];
    const float* c2bu   = (const float*)d_in[25];
    const float* headW1 = (const float*)d_in[26];
    const float* headb1 = (const float*)d_in[27];
    const float* headW2 = (const float*)d_in[28];
    const float* headb2 = (const float*)d_in[29];
    float* out = (float*)d_out;

    float *hshd, *aggr, *inv1, *inv2, *st1, *st2, *b2f;
    __nv_bfloat16 *whi, *wlo, *ahi, *alo;
    cudaGetSymbolAddress((void**)&hshd, g_hshd);
    cudaGetSymbolAddress((void**)&aggr, g_aggr);
    cudaGetSymbolAddress((void**)&inv1, g_inv1);
    cudaGetSymbolAddress((void**)&inv2, g_inv2);
    cudaGetSymbolAddress((void**)&st1,  g_stat1);
    cudaGetSymbolAddress((void**)&st2,  g_stat2);
    cudaGetSymbolAddress((void**)&b2f,  g_b2f);
    cudaGetSymbolAddress((void**)&whi,  g_whi);
    cudaGetSymbolAddress((void**)&wlo,  g_wlo);
    cudaGetSymbolAddress((void**)&ahi,  g_ahi);
    cudaGetSymbolAddress((void**)&alo,  g_alo);

    const int GB = (NN + 127) / 128;
    const dim3 G1(GB, 1), G2(GB, 2);
    const int EGRID = 1184;
    const int MM_SMEM = 65536;
    cudaFuncSetAttribute(mma_gemm<0, 1>, cudaFuncAttributeMaxDynamicSharedMemorySize, MM_SMEM);
    cudaFuncSetAttribute(mma_gemm<1, 0>, cudaFuncAttributeMaxDynamicSharedMemorySize, MM_SMEM);

    // weight offsets in g_whi/g_wlo ([N=128][K] layout); W2F at 0 via fold2w
    const int OFF_W2F  = 0;
    const int OFF_C1S  = 32768,  OFF_C1D = 81920,  OFF_C1U = 131072;
    const int OFF_C2S  = 229376, OFF_C2D = 278528, OFF_C2U = 327680;
    const int OFF_HA   = 425984, OFF_HB  = 442368;

    WSpecs ws;   // 14 entries
    for (int l = 0; l < 3; l++) {
        ws.src[0 + l]  = c1Ws + l * 16384; ws.K[0 + l]  = 128; ws.off[0 + l]  = OFF_C1S + l * 16384;
        ws.src[3 + l]  = c1Wd + l * 16384; ws.K[3 + l]  = 128; ws.off[3 + l]  = OFF_C1D + l * 16384;
        ws.src[6 + l]  = c1Wu + l * 32768; ws.K[6 + l]  = 256; ws.off[6 + l]  = OFF_C1U + l * 32768;
        ws.src[9 + l]  = c2Ws + l * 16384; ws.K[9 + l]  = 128; ws.off[9 + l]  = OFF_C2S + l * 16384;
    }
    ws.src[12] = headW1;         ws.K[12] = 128; ws.off[12] = OFF_HA;
    ws.src[13] = headW1 + 16384; ws.K[13] = 128; ws.off[13] = OFF_HB;
    WSpecs ws2;  // 6 entries
    for (int l = 0; l < 3; l++) {
        ws2.src[l]     = c2Wd + l * 16384; ws2.K[l]     = 128; ws2.off[l]     = OFF_C2D + l * 16384;
        ws2.src[3 + l] = c2Wu + l * 32768; ws2.K[3 + l] = 256; ws2.off[3 + l] = OFF_C2U + l * 32768;
    }

    // -------- lin_node (4th kernel = mma_gemm lin2 -> ncu capture) ----------
    cudaMemsetAsync(st1, 0, 32 * sizeof(float));
    cudaMemsetAsync(st2, 0, 2 * DIMF * sizeof(float));
    stats13_kernel<<<592, 256>>>(x, st1);                                     // k1
    h1_kernel<<<(NN + H1_ROWS - 1) / H1_ROWS, 256>>>(x, st1, bn1g, bn1b,
                                                     lin1W, lin1b, ahi, alo, st2); // k2
    fold2w_kernel<<<DIMF, DIM>>>(st2, bn2g, bn2b, lin2W, lin2b, whi, wlo, b2f);    // k3
    mma_gemm<0, 1><<<G1, 256, MM_SMEM>>>(ahi, alo, whi, wlo, OFF_W2F, 0,
                                         b2f, 1, nullptr, 0, 0, ahi, alo, NN, 256); // k4 <- ncu
    wconv_kernel<<<dim3(14, 8), 256>>>(ws, whi, wlo);                              // k5
    wconv_kernel<<<dim3(6, 8), 256>>>(ws2, whi, wlo);                              // k6

    // -------- degree counts --------
    cudaMemsetAsync(inv1, 0, NN * sizeof(float));
    cudaMemsetAsync(inv2, 0, NN * sizeof(float));
    count_kernel<<<(EE + 255) / 256, 256>>>(ei + EE, EE, inv1);
    count_kernel<<<(E3N + 255) / 256, 256>>>(ei3 + E3N, E3N, inv2);
    count_kernel<<<(E3N + 255) / 256, 256>>>(ei3, E3N, inv2);
    inv_kernel<<<(NN + 255) / 256, 256>>>(inv1, NN);
    inv_kernel<<<(NN + 255) / 256, 256>>>(inv2, NN);

    // -------- conv1 x3 --------
    for (int l = 0; l < 3; l++) {
        mma_gemm<1, 0><<<G2, 256, MM_SMEM>>>(ahi, alo, whi, wlo,
                                             OFF_C1S + l * 16384, OFF_C1D + l * 16384,
                                             nullptr, 0, hshd, 256, 0,
                                             nullptr, nullptr, NN, 128);
        cudaMemsetAsync(aggr, 0, (size_t)NN * 128 * sizeof(float));
        edge_msg_kernel<8, false><<<EGRID, 256>>>(hshd, ei, eattr, nullptr,
                                                  c1We + l * 8 * 128, c1bm + l * 128,
                                                  aggr, EE, 0);
        aconv_kernel<<<(NN * 16 + 255) / 256, 256>>>(aggr, inv1, ahi, alo);
        mma_gemm<0, 1><<<G1, 256, MM_SMEM>>>(ahi, alo, whi, wlo,
                                             OFF_C1U + l * 32768, 0,
                                             c1bu + l * 128, 1, nullptr, 0, 0,
                                             ahi, alo, NN, 256);
    }

    // -------- conv2 x3 --------
    for (int l = 0; l < 3; l++) {
        mma_gemm<1, 0><<<G2, 256, MM_SMEM>>>(ahi, alo, whi, wlo,
                                             OFF_C2S + l * 16384, OFF_C2D + l * 16384,
                                             nullptr, 0, hshd, 256, 0,
                                             nullptr, nullptr, NN, 128);
        cudaMemsetAsync(aggr, 0, (size_t)NN * 128 * sizeof(float));
        edge_msg_kernel<16, true><<<EGRID, 256>>>(hshd, ei3, ea3, ea4,
                                                  c2We + l * 16 * 128, c2bm + l * 128,
                                                  aggr, 2 * E3N, E3N);
        aconv_kernel<<<(NN * 16 + 255) / 256, 256>>>(aggr, inv2, ahi, alo);
        mma_gemm<0, 1><<<G1, 256, MM_SMEM>>>(ahi, alo, whi, wlo,
                                             OFF_C2U + l * 32768, 0,
                                             c2bu + l * 128, 1, nullptr, 0, 0,
                                             ahi, alo, NN, 256);
    }

    // -------- head --------
    mma_gemm<1, 0><<<G2, 256, MM_SMEM>>>(ahi, alo, whi, wlo,
                                         OFF_HA, OFF_HB,
                                         nullptr, 0, hshd, 256, 0,
                                         nullptr, nullptr, NN, 128);
    head_kernel<<<EGRID, 256>>>(hshd, ei3, ea3, ea4,
                                headW1 + 256 * 128, headb1, headW2, headb2, out);
}

// round 15
// speedup vs baseline: 1.4617x; 1.1093x over previous
#include <cuda_runtime.h>
#include <cuda_bf16.h>
#include <cstdint>

#define NN      100000
#define EE      800000
#define E3N     400000
#define NODE_IN 13
#define DIM     128
#define DIMF    256

// ---------------- scratch (static __device__; no allocation allowed) -------
__device__ float g_hshd[(size_t)NN * DIMF];
__device__ float g_aggr[(size_t)NN * DIM];
__device__ float g_inv1[NN];
__device__ float g_inv2[NN];
__device__ float g_stat1[32];
__device__ float g_stat2[2 * DIMF];
__device__ float g_b2f[DIM];
// activations, bf16 hi/lo split, [row][256] (padded rows for tail blocks)
__device__ __nv_bfloat16 g_ahi[(size_t)(NN + 128) * DIMF];
__device__ __nv_bfloat16 g_alo[(size_t)(NN + 128) * DIMF];
// pre-converted weights, transposed [N=128][K] bf16, hi/lo split
#define WTOT 458752
__device__ __nv_bfloat16 g_whi[WTOT];
__device__ __nv_bfloat16 g_wlo[WTOT];

// ---------------- small helpers ---------------------------------------------
__device__ __forceinline__ unsigned smem_u32(const void* p)
{
    return (unsigned)__cvta_generic_to_shared(p);
}
__device__ __forceinline__ void red_add_v4(float* p, float4 v)
{
    asm volatile("red.global.add.v4.f32 [%0], {%1, %2, %3, %4};"
                 :: "l"(p), "f"(v.x), "f"(v.y), "f"(v.z), "f"(v.w) : "memory");
}

#define SMEM_SWIZZLE_128B(o) ((o) ^ (((o) >> 3) & 0x70))

// split x,y -> hi/lo bf16x2 packed
__device__ __forceinline__ void split2(float x, float y, uint32_t& hi, uint32_t& lo)
{
    __nv_bfloat16 hx = __float2bfloat16(x), hy = __float2bfloat16(y);
    float rx = x - __bfloat162float(hx);
    float ry = y - __bfloat162float(hy);
    __nv_bfloat16 lx = __float2bfloat16(rx), ly = __float2bfloat16(ry);
    hi = (uint32_t)__bfloat16_as_ushort(hx) | ((uint32_t)__bfloat16_as_ushort(hy) << 16);
    lo = (uint32_t)__bfloat16_as_ushort(lx) | ((uint32_t)__bfloat16_as_ushort(ly) << 16);
}
__device__ __forceinline__ void split1(float x, __nv_bfloat16& h, __nv_bfloat16& l)
{
    h = __float2bfloat16(x);
    l = __float2bfloat16(x - __bfloat162float(h));
}

#define LDM4(r, addr) \
    asm volatile("ldmatrix.sync.aligned.m8n8.x4.shared.b16 {%0,%1,%2,%3}, [%4];" \
                 : "=r"((r)[0]), "=r"((r)[1]), "=r"((r)[2]), "=r"((r)[3]) : "r"(addr))

#define MMA16816(d, a, b0, b1) \
    asm volatile("mma.sync.aligned.m16n8k16.row.col.f32.bf16.bf16.f32 " \
                 "{%0,%1,%2,%3}, {%4,%5,%6,%7}, {%8,%9}, {%0,%1,%2,%3};" \
                 : "+f"((d)[0]), "+f"((d)[1]), "+f"((d)[2]), "+f"((d)[3]) \
                 : "r"((a)[0]), "r"((a)[1]), "r"((a)[2]), "r"((a)[3]), \
                   "r"(b0), "r"(b1))

// ---------------- column stats of x (13 cols) ------------------------------
__global__ void stats13_kernel(const float* __restrict__ x, float* __restrict__ stat)
{
    float ls[NODE_IN], lq[NODE_IN];
#pragma unroll
    for (int c = 0; c < NODE_IN; c++) { ls[c] = 0.f; lq[c] = 0.f; }
    int stride = gridDim.x * blockDim.x;
    for (int r = blockIdx.x * blockDim.x + threadIdx.x; r < NN; r += stride) {
#pragma unroll
        for (int c = 0; c < NODE_IN; c++) {
            float v = x[(size_t)r * NODE_IN + c];
            ls[c] += v; lq[c] += v * v;
        }
    }
    __shared__ float ss[2 * NODE_IN];
    if (threadIdx.x < 2 * NODE_IN) ss[threadIdx.x] = 0.f;
    __syncthreads();
#pragma unroll
    for (int c = 0; c < NODE_IN; c++) {
        atomicAdd(&ss[c], ls[c]);
        atomicAdd(&ss[NODE_IN + c], lq[c]);
    }
    __syncthreads();
    if (threadIdx.x < 2 * NODE_IN) atomicAdd(&stat[threadIdx.x], ss[threadIdx.x]);
}

// ------- h1 = relu(bn1(x)@W1+b1) -> bf16 hi/lo directly (cols 0..255) -------
#define H1_ROWS 64
__global__ __launch_bounds__(256)
void h1_kernel(const float* __restrict__ x, const float* __restrict__ stat,
               const float* __restrict__ bn1g, const float* __restrict__ bn1b,
               const float* __restrict__ W1, const float* __restrict__ b1,
               __nv_bfloat16* __restrict__ ahi, __nv_bfloat16* __restrict__ alo,
               float* __restrict__ stat2)
{
    __shared__ float xs[H1_ROWS * NODE_IN];
    int t = threadIdx.x;
    float w[NODE_IN];
    float bb = b1[t];
#pragma unroll
    for (int k = 0; k < NODE_IN; k++) {
        float m = stat[k] * (1.0f / NN);
        float v = stat[NODE_IN + k] * (1.0f / NN) - m * m;
        float a = bn1g[k] * rsqrtf(v + 1e-5f);
        float be = bn1b[k] - m * a;
        float wv = W1[k * DIMF + t];
        w[k] = a * wv;
        bb += be * wv;
    }
    int r0 = blockIdx.x * H1_ROWS;
    int nr = min(H1_ROWS, NN - r0);
    for (int i = t; i < nr * NODE_IN; i += 256)
        xs[i] = x[(size_t)r0 * NODE_IN + i];
    __syncthreads();
    float s = 0.f, q = 0.f;
    for (int r = 0; r < nr; r++) {
        float acc = bb;
#pragma unroll
        for (int k = 0; k < NODE_IN; k++) acc = fmaf(xs[r * NODE_IN + k], w[k], acc);
        acc = fmaxf(acc, 0.f);
        __nv_bfloat16 h, l;
        split1(acc, h, l);
        ahi[(size_t)(r0 + r) * DIMF + t] = h;
        alo[(size_t)(r0 + r) * DIMF + t] = l;
        s += acc; q += acc * acc;
    }
    atomicAdd(&stat2[t], s);
    atomicAdd(&stat2[DIMF + t], q);
}

// -------- fold bn2 into lin2, emit transposed bf16 hi/lo + bias --------------
__global__ void fold2w_kernel(const float* __restrict__ stat2,
                              const float* __restrict__ g, const float* __restrict__ b,
                              const float* __restrict__ W2, const float* __restrict__ b2,
                              __nv_bfloat16* __restrict__ whi, __nv_bfloat16* __restrict__ wlo,
                              float* __restrict__ b2f)
{
    int k = blockIdx.x;   // 0..255 input channel
    int j = threadIdx.x;  // 0..127 output channel
    __shared__ float al;
    if (j == 0) {
        float m = stat2[k] * (1.0f / NN);
        float v = stat2[DIMF + k] * (1.0f / NN) - m * m;
        al = g[k] * rsqrtf(v + 1e-5f);
    }
    __syncthreads();
    float wv = al * W2[k * DIM + j];
    __nv_bfloat16 h, l;
    split1(wv, h, l);
    whi[(size_t)j * 256 + k] = h;   // OFF_W2F = 0, [n=j][k], K=256
    wlo[(size_t)j * 256 + k] = l;
    if (k == 0) {
        float acc = b2[j];
        for (int kk = 0; kk < DIMF; kk++) {
            float m = stat2[kk] * (1.0f / NN);
            float v = stat2[DIMF + kk] * (1.0f / NN) - m * m;
            float a = g[kk] * rsqrtf(v + 1e-5f);
            float be = b[kk] - m * a;
            acc += be * W2[kk * DIM + j];
        }
        b2f[j] = acc;
    }
}

// ---------------- weight pre-convert: [K][128] fp32 -> [128][K] bf16 hi/lo --
struct WSpecs {
    const float* src[16];
    int K[16];
    int off[16];
};
__global__ void wconv_kernel(WSpecs s, __nv_bfloat16* __restrict__ whi,
                             __nv_bfloat16* __restrict__ wlo)
{
    const float* W = s.src[blockIdx.x];
    int K = s.K[blockIdx.x];
    int off = s.off[blockIdx.x];
    int slab = blockIdx.y * 16;
    for (int idx = threadIdx.x; idx < K * 16; idx += blockDim.x) {
        int n = slab + idx / K;
        int k = idx % K;
        float x = W[(size_t)k * 128 + n];
        __nv_bfloat16 h, l;
        split1(x, h, l);
        whi[off + (size_t)n * K + k] = h;
        wlo[off + (size_t)n * K + k] = l;
    }
}

// ---- aconv: aggr[row][128] * inv[row] -> ahi/alo cols 128..255 --------------
__global__ __launch_bounds__(256)
void aconv_kernel(const float* __restrict__ src, const float* __restrict__ scale,
                  __nv_bfloat16* __restrict__ ahi, __nv_bfloat16* __restrict__ alo)
{
    int idx = blockIdx.x * 256 + threadIdx.x;      // 8 elems per thread
    int row = idx >> 4;
    int g   = idx & 15;
    if (row >= NN) return;
    float s = scale[row];
    const float4* p = reinterpret_cast<const float4*>(src + (size_t)row * 128 + g * 8);
    float4 a0 = p[0], a1 = p[1];
    a0.x *= s; a0.y *= s; a0.z *= s; a0.w *= s;
    a1.x *= s; a1.y *= s; a1.z *= s; a1.w *= s;
    uint4 hi, lo;
    split2(a0.x, a0.y, hi.x, lo.x);
    split2(a0.z, a0.w, hi.y, lo.y);
    split2(a1.x, a1.y, hi.z, lo.z);
    split2(a1.z, a1.w, hi.w, lo.w);
    size_t o = (size_t)row * 256 + 128 + g * 8;
    *reinterpret_cast<uint4*>(ahi + o) = hi;
    *reinterpret_cast<uint4*>(alo + o) = lo;
}

// ---------------- degree counting -------------------------------------------
__global__ void count_kernel(const int* __restrict__ dst, int n, float* __restrict__ cnt)
{
    int i = blockIdx.x * blockDim.x + threadIdx.x;
    if (i < n) atomicAdd(&cnt[dst[i]], 1.0f);
}
__global__ void inv_kernel(float* __restrict__ c, int n)
{
    int i = blockIdx.x * blockDim.x + threadIdx.x;
    if (i < n) c[i] = 1.0f / fmaxf(c[i], 1.0f);
}

// ---------------- warp-MMA bf16 split-2 GEMM --------------------------------
// A: bf16 hi/lo [row][256] (cols 0..K-1). W: pre-split bf16 [N=128][K].
// DUAL=1: blockIdx.y picks (bOff0, col 0)/(bOff1, col 128); K=128.
// OUTW=0: write fp32 C[:, colOff:+128]. OUTW=1: write bf16 hi/lo cols 0..127
//         of ohi/olo in place (safe: each CTA writes only rows it reads).
// CTA 128x128 tile, 8 warps (4M x 2N), warp tile 32x64, K chunks of 64.
// __launch_bounds__(256, 2): cap regs at 128 so 2 CTAs/SM co-reside
// (R12 profile: regs=130 -> 1 CTA/SM, occ 12.4%, tensor 30%).
// acc += Ahi*Bhi + Ahi*Blo + Alo*Bhi
template<int DUAL, int OUTW>
__global__ __launch_bounds__(256, 2)
void mma_gemm(const __nv_bfloat16* __restrict__ ahi,
              const __nv_bfloat16* __restrict__ alo,
              const __nv_bfloat16* __restrict__ whi,
              const __nv_bfloat16* __restrict__ wlo,
              size_t bOff0, size_t bOff1,
              const float* __restrict__ bias, int relu,
              float* __restrict__ C, int ldc, int colOff,
              __nv_bfloat16* __restrict__ ohi, __nv_bfloat16* __restrict__ olo,
              int Nrows, int K)
{
    extern __shared__ unsigned char dsm[];
    const int OFF_AH = 0, OFF_AL = 16384, OFF_BH = 32768, OFF_BL = 49152;
    int tid  = threadIdx.x;
    int wid  = tid >> 5, lane = tid & 31;
    int warpM = wid & 3, warpN = wid >> 2;
    size_t bOff = bOff0;
    if (DUAL && blockIdx.y == 1) { bOff = bOff1; colOff += 128; }
    int brow = blockIdx.x * 128;

    int lrow  = tid >> 1;
    int lhalf = tid & 1;
    int grow  = brow + lrow;   // may exceed Nrows; buffer padded, outputs guarded

    float acc[16][4];
#pragma unroll
    for (int i = 0; i < 16; i++)
#pragma unroll
        for (int j = 0; j < 4; j++) acc[i][j] = 0.f;

    const int nch = K / 64;
    for (int c = 0; c < nch; c++) {
        if (c > 0) __syncthreads();
        // ---- A chunk: pure bf16 copy, swizzled ----
        {
            const uint4* ph = reinterpret_cast<const uint4*>(ahi + (size_t)grow * 256 + c * 64 + lhalf * 32);
            const uint4* pl = reinterpret_cast<const uint4*>(alo + (size_t)grow * 256 + c * 64 + lhalf * 32);
#pragma unroll
            for (int g = 0; g < 4; g++) {
                uint32_t so = SMEM_SWIZZLE_128B((uint32_t)(lrow * 128 + lhalf * 64 + g * 16));
                *reinterpret_cast<uint4*>(dsm + OFF_AH + so) = ph[g];
                *reinterpret_cast<uint4*>(dsm + OFF_AL + so) = pl[g];
            }
        }
        // ---- B chunk ----
        {
            const uint4* bh = reinterpret_cast<const uint4*>(whi + bOff + (size_t)lrow * K + c * 64 + lhalf * 32);
            const uint4* bl = reinterpret_cast<const uint4*>(wlo + bOff + (size_t)lrow * K + c * 64 + lhalf * 32);
#pragma unroll
            for (int g = 0; g < 4; g++) {
                uint32_t so = SMEM_SWIZZLE_128B((uint32_t)(lrow * 128 + lhalf * 64 + g * 16));
                *reinterpret_cast<uint4*>(dsm + OFF_BH + so) = bh[g];
                *reinterpret_cast<uint4*>(dsm + OFF_BL + so) = bl[g];
            }
        }
        __syncthreads();
        // ---- compute: 4 k16 steps ----
#pragma unroll
        for (int k16 = 0; k16 < 4; k16++) {
            uint32_t ah[2][4], al[2][4];
#pragma unroll
            for (int tm = 0; tm < 2; tm++) {
                int r  = warpM * 32 + tm * 16 + (lane & 7) + ((lane >> 3) & 1) * 8;
                int cb = k16 * 32 + ((lane >> 4) & 1) * 16;
                uint32_t so = SMEM_SWIZZLE_128B((uint32_t)(r * 128 + cb));
                LDM4(ah[tm], smem_u32(dsm + OFF_AH + so));
                LDM4(al[tm], smem_u32(dsm + OFF_AL + so));
            }
            uint32_t bh[4][4], bl[4][4];
#pragma unroll
            for (int bq = 0; bq < 4; bq++) {
                int n  = warpN * 64 + bq * 16 + (lane & 7) + ((lane >> 4) & 1) * 8;
                int cb = k16 * 32 + ((lane >> 3) & 1) * 16;
                uint32_t so = SMEM_SWIZZLE_128B((uint32_t)(n * 128 + cb));
                LDM4(bh[bq], smem_u32(dsm + OFF_BH + so));
                LDM4(bl[bq], smem_u32(dsm + OFF_BL + so));
            }
#pragma unroll
            for (int tm = 0; tm < 2; tm++)
#pragma unroll
                for (int tn = 0; tn < 8; tn++) {
                    float* d = acc[tm * 8 + tn];
                    uint32_t* B  = &bh[tn >> 1][(tn & 1) * 2];
                    uint32_t* Bl = &bl[tn >> 1][(tn & 1) * 2];
                    MMA16816(d, ah[tm], B[0],  B[1]);
                    MMA16816(d, ah[tm], Bl[0], Bl[1]);
                    MMA16816(d, al[tm], B[0],  B[1]);
                }
        }
    }

    // ---- epilogue ----
#pragma unroll
    for (int tm = 0; tm < 2; tm++)
#pragma unroll
        for (int tn = 0; tn < 8; tn++) {
            float* d = acc[tm * 8 + tn];
            int r0   = brow + warpM * 32 + tm * 16 + (lane >> 2);
            int colL = warpN * 64 + tn * 8 + (lane & 3) * 2;   // 0..127 local
            float b0 = 0.f, b1v = 0.f;
            if (bias) {
                float2 bb = *reinterpret_cast<const float2*>(bias + colL);
                b0 = bb.x; b1v = bb.y;
            }
            float o0 = d[0] + b0, o1 = d[1] + b1v;
            float o2 = d[2] + b0, o3 = d[3] + b1v;
            if (relu) {
                o0 = fmaxf(o0, 0.f); o1 = fmaxf(o1, 0.f);
                o2 = fmaxf(o2, 0.f); o3 = fmaxf(o3, 0.f);
            }
            if (OUTW == 0) {
                int col = colOff + colL;
                if (r0 < Nrows)
                    *reinterpret_cast<float2*>(C + (size_t)r0 * ldc + col) = make_float2(o0, o1);
                if (r0 + 8 < Nrows)
                    *reinterpret_cast<float2*>(C + (size_t)(r0 + 8) * ldc + col) = make_float2(o2, o3);
            } else {
                uint32_t h01, l01, h23, l23;
                split2(o0, o1, h01, l01);
                split2(o2, o3, h23, l23);
                if (r0 < Nrows) {
                    *reinterpret_cast<uint32_t*>(ohi + (size_t)r0 * 256 + colL) = h01;
                    *reinterpret_cast<uint32_t*>(olo + (size_t)r0 * 256 + colL) = l01;
                }
                if (r0 + 8 < Nrows) {
                    *reinterpret_cast<uint32_t*>(ohi + (size_t)(r0 + 8) * 256 + colL) = h23;
                    *reinterpret_cast<uint32_t*>(olo + (size_t)(r0 + 8) * 256 + colL) = l23;
                }
            }
        }
}

// ---------------- edge message + scatter-add (grid-stride) ------------------
template<int EDIM, bool SYM>
__global__ __launch_bounds__(256)
void edge_msg_kernel(const float* __restrict__ hshd,
                     const int* __restrict__ ei,
                     const float* __restrict__ ea, const float* __restrict__ eb,
                     const float* __restrict__ We, const float* __restrict__ bm,
                     float* __restrict__ aggr, int Etot, int Ehalf)
{
    __shared__ float Wes[EDIM * 128];
    __shared__ float bms[128];
    int tid = threadIdx.x;
    for (int i = tid; i < EDIM * 128; i += 256) Wes[i] = We[i];
    if (tid < 128) bms[tid] = bm[tid];
    __syncthreads();
    int wglob = blockIdx.x * 8 + (tid >> 5);
    int lane  = tid & 31;
    int step  = gridDim.x * 8;
    int c = lane << 2;
    for (int e = wglob; e < Etot; e += step) {
        int src, dst, eidx;
        if (SYM) {
            src = ei[e];
            if (e < Ehalf) { dst = ei[e + Ehalf]; eidx = e; }
            else           { dst = ei[e - Ehalf]; eidx = e - Ehalf; }
        } else {
            src = ei[e]; dst = ei[Etot + e]; eidx = e;
        }
        float aval = 0.f;
        if (SYM) {
            if (lane < 8)       aval = ea[(size_t)eidx * 8 + lane];
            else if (lane < 16) aval = eb[(size_t)eidx * 8 + (lane - 8)];
        } else {
            if (lane < EDIM)    aval = ea[(size_t)eidx * EDIM + lane];
        }
        float4 m = *reinterpret_cast<const float4*>(bms + c);
        float4 a = *reinterpret_cast<const float4*>(hshd + (size_t)src * 256 + c);
        float4 b = *reinterpret_cast<const float4*>(hshd + (size_t)dst * 256 + 128 + c);
        m.x += a.x + b.x; m.y += a.y + b.y; m.z += a.z + b.z; m.w += a.w + b.w;
#pragma unroll
        for (int k = 0; k < EDIM; k++) {
            float av = __shfl_sync(0xffffffffu, aval, k);
            float4 w = *reinterpret_cast<const float4*>(Wes + k * 128 + c);
            m.x = fmaf(av, w.x, m.x); m.y = fmaf(av, w.y, m.y);
            m.z = fmaf(av, w.z, m.z); m.w = fmaf(av, w.w, m.w);
        }
        m.x = fmaxf(m.x, 0.f); m.y = fmaxf(m.y, 0.f);
        m.z = fmaxf(m.z, 0.f); m.w = fmaxf(m.w, 0.f);
        red_add_v4(aggr + (size_t)dst * 128 + c, m);
    }
}

// ---------------- head: per coupling edge (grid-stride) ----------------------
__global__ __launch_bounds__(256)
void head_kernel(const float* __restrict__ g12, const int* __restrict__ ei3,
                 const float* __restrict__ ea3, const float* __restrict__ ea4,
                 const float* __restrict__ Wtail, const float* __restrict__ b1,
                 const float* __restrict__ W2, const float* __restrict__ b2,
                 float* __restrict__ out)
{
    __shared__ float Ws[16 * 128];
    __shared__ float b1s[128];
    __shared__ float W2s[128];
    int tid = threadIdx.x;
    for (int i = tid; i < 16 * 128; i += 256) Ws[i] = Wtail[i];
    if (tid < 128) { b1s[tid] = b1[tid]; W2s[tid] = W2[tid]; }
    __syncthreads();
    int wglob = blockIdx.x * 8 + (tid >> 5);
    int lane  = tid & 31;
    int step  = gridDim.x * 8;
    int c = lane << 2;
    for (int e = wglob; e < E3N; e += step) {
        int s = ei3[e], d = ei3[E3N + e];
        float aval = 0.f;
        if (lane < 8)       aval = ea3[(size_t)e * 8 + lane];
        else if (lane < 16) aval = ea4[(size_t)e * 8 + (lane - 8)];
        float4 v = *reinterpret_cast<const float4*>(b1s + c);
        float4 a = *reinterpret_cast<const float4*>(g12 + (size_t)s * 256 + c);
        float4 b = *reinterpret_cast<const float4*>(g12 + (size_t)d * 256 + 128 + c);
        v.x += a.x + b.x; v.y += a.y + b.y; v.z += a.z + b.z; v.w += a.w + b.w;
#pragma unroll
        for (int k = 0; k < 16; k++) {
            float av = __shfl_sync(0xffffffffu, aval, k);
            float4 w = *reinterpret_cast<const float4*>(Ws + k * 128 + c);
            v.x = fmaf(av, w.x, v.x); v.y = fmaf(av, w.y, v.y);
            v.z = fmaf(av, w.z, v.z); v.w = fmaf(av, w.w, v.w);
        }
        v.x = fmaxf(v.x, 0.f); v.y = fmaxf(v.y, 0.f);
        v.z = fmaxf(v.z, 0.f); v.w = fmaxf(v.w, 0.f);
        float4 w2 = *reinterpret_cast<const float4*>(W2s + c);
        float p = v.x * w2.x + v.y * w2.y + v.z * w2.z + v.w * w2.w;
#pragma unroll
        for (int o = 16; o > 0; o >>= 1) p += __shfl_xor_sync(0xffffffffu, p, o);
        if (lane == 0) out[e] = p + b2[0];
    }
}

// ---------------- host orchestration ----------------------------------------
extern "C" void kernel_launch(void* const* d_in, const int* in_sizes, int n_in,
                              void* d_out, int out_size)
{
    const float* x      = (const float*)d_in[0];
    const int*   ei     = (const int*)  d_in[1];
    const float* eattr  = (const float*)d_in[2];
    const int*   ei3    = (const int*)  d_in[3];
    const float* ea3    = (const float*)d_in[4];
    const float* ea4    = (const float*)d_in[5];
    const float* bn1g   = (const float*)d_in[6];
    const float* bn1b   = (const float*)d_in[7];
    const float* lin1W  = (const float*)d_in[8];
    const float* lin1b  = (const float*)d_in[9];
    const float* bn2g   = (const float*)d_in[10];
    const float* bn2b   = (const float*)d_in[11];
    const float* lin2W  = (const float*)d_in[12];
    const float* lin2b  = (const float*)d_in[13];
    const float* c1Ws   = (const float*)d_in[14];
    const float* c1Wd   = (const float*)d_in[15];
    const float* c1We   = (const float*)d_in[16];
    const float* c1bm   = (const float*)d_in[17];
    const float* c1Wu   = (const float*)d_in[18];
    const float* c1bu   = (const float*)d_in[19];
    const float* c2Ws   = (const float*)d_in[20];
    const float* c2Wd   = (const float*)d_in[21];
    const float* c2We   = (const float*)d_in[22];
    const float* c2bm   = (const float*)d_in[23];
    const float* c2Wu   = (const float*)d_in[24];
    const float* c2bu   = (const float*)d_in[25];
    const float* headW1 = (const float*)d_in[26];
    const float* headb1 = (const float*)d_in[27];
    const float* headW2 = (const float*)d_in[28];
    const float* headb2 = (const float*)d_in[29];
    float* out = (float*)d_out;

    float *hshd, *aggr, *inv1, *inv2, *st1, *st2, *b2f;
    __nv_bfloat16 *whi, *wlo, *ahi, *alo;
    cudaGetSymbolAddress((void**)&hshd, g_hshd);
    cudaGetSymbolAddress((void**)&aggr, g_aggr);
    cudaGetSymbolAddress((void**)&inv1, g_inv1);
    cudaGetSymbolAddress((void**)&inv2, g_inv2);
    cudaGetSymbolAddress((void**)&st1,  g_stat1);
    cudaGetSymbolAddress((void**)&st2,  g_stat2);
    cudaGetSymbolAddress((void**)&b2f,  g_b2f);
    cudaGetSymbolAddress((void**)&whi,  g_whi);
    cudaGetSymbolAddress((void**)&wlo,  g_wlo);
    cudaGetSymbolAddress((void**)&ahi,  g_ahi);
    cudaGetSymbolAddress((void**)&alo,  g_alo);

    const int GB = (NN + 127) / 128;
    const dim3 G1(GB, 1), G2(GB, 2);
    const int EGRID = 1184;
    const int MM_SMEM = 65536;
    cudaFuncSetAttribute(mma_gemm<0, 1>, cudaFuncAttributeMaxDynamicSharedMemorySize, MM_SMEM);
    cudaFuncSetAttribute(mma_gemm<1, 0>, cudaFuncAttributeMaxDynamicSharedMemorySize, MM_SMEM);

    // weight offsets in g_whi/g_wlo ([N=128][K] layout); W2F at 0 via fold2w
    const int OFF_W2F  = 0;
    const int OFF_C1S  = 32768,  OFF_C1D = 81920,  OFF_C1U = 131072;
    const int OFF_C2S  = 229376, OFF_C2D = 278528, OFF_C2U = 327680;
    const int OFF_HA   = 425984, OFF_HB  = 442368;

    WSpecs ws;   // 14 entries
    for (int l = 0; l < 3; l++) {
        ws.src[0 + l]  = c1Ws + l * 16384; ws.K[0 + l]  = 128; ws.off[0 + l]  = OFF_C1S + l * 16384;
        ws.src[3 + l]  = c1Wd + l * 16384; ws.K[3 + l]  = 128; ws.off[3 + l]  = OFF_C1D + l * 16384;
        ws.src[6 + l]  = c1Wu + l * 32768; ws.K[6 + l]  = 256; ws.off[6 + l]  = OFF_C1U + l * 32768;
        ws.src[9 + l]  = c2Ws + l * 16384; ws.K[9 + l]  = 128; ws.off[9 + l]  = OFF_C2S + l * 16384;
    }
    ws.src[12] = headW1;         ws.K[12] = 128; ws.off[12] = OFF_HA;
    ws.src[13] = headW1 + 16384; ws.K[13] = 128; ws.off[13] = OFF_HB;
    WSpecs ws2;  // 6 entries
    for (int l = 0; l < 3; l++) {
        ws2.src[l]     = c2Wd + l * 16384; ws2.K[l]     = 128; ws2.off[l]     = OFF_C2D + l * 16384;
        ws2.src[3 + l] = c2Wu + l * 32768; ws2.K[3 + l] = 256; ws2.off[3 + l] = OFF_C2U + l * 32768;
    }

    // -------- lin_node (4th kernel = mma_gemm lin2 -> ncu capture) ----------
    cudaMemsetAsync(st1, 0, 32 * sizeof(float));
    cudaMemsetAsync(st2, 0, 2 * DIMF * sizeof(float));
    stats13_kernel<<<592, 256>>>(x, st1);                                     // k1
    h1_kernel<<<(NN + H1_ROWS - 1) / H1_ROWS, 256>>>(x, st1, bn1g, bn1b,
                                                     lin1W, lin1b, ahi, alo, st2); // k2
    fold2w_kernel<<<DIMF, DIM>>>(st2, bn2g, bn2b, lin2W, lin2b, whi, wlo, b2f);    // k3
    mma_gemm<0, 1><<<G1, 256, MM_SMEM>>>(ahi, alo, whi, wlo, OFF_W2F, 0,
                                         b2f, 1, nullptr, 0, 0, ahi, alo, NN, 256); // k4 <- ncu
    wconv_kernel<<<dim3(14, 8), 256>>>(ws, whi, wlo);                              // k5
    wconv_kernel<<<dim3(6, 8), 256>>>(ws2, whi, wlo);                              // k6

    // -------- degree counts --------
    cudaMemsetAsync(inv1, 0, NN * sizeof(float));
    cudaMemsetAsync(inv2, 0, NN * sizeof(float));
    count_kernel<<<(EE + 255) / 256, 256>>>(ei + EE, EE, inv1);
    count_kernel<<<(E3N + 255) / 256, 256>>>(ei3 + E3N, E3N, inv2);
    count_kernel<<<(E3N + 255) / 256, 256>>>(ei3, E3N, inv2);
    inv_kernel<<<(NN + 255) / 256, 256>>>(inv1, NN);
    inv_kernel<<<(NN + 255) / 256, 256>>>(inv2, NN);

    // -------- conv1 x3 --------
    for (int l = 0; l < 3; l++) {
        mma_gemm<1, 0><<<G2, 256, MM_SMEM>>>(ahi, alo, whi, wlo,
                                             OFF_C1S + l * 16384, OFF_C1D + l * 16384,
                                             nullptr, 0, hshd, 256, 0,
                                             nullptr, nullptr, NN, 128);
        cudaMemsetAsync(aggr, 0, (size_t)NN * 128 * sizeof(float));
        edge_msg_kernel<8, false><<<EGRID, 256>>>(hshd, ei, eattr, nullptr,
                                                  c1We + l * 8 * 128, c1bm + l * 128,
                                                  aggr, EE, 0);
        aconv_kernel<<<(NN * 16 + 255) / 256, 256>>>(aggr, inv1, ahi, alo);
        mma_gemm<0, 1><<<G1, 256, MM_SMEM>>>(ahi, alo, whi, wlo,
                                             OFF_C1U + l * 32768, 0,
                                             c1bu + l * 128, 1, nullptr, 0, 0,
                                             ahi, alo, NN, 256);
    }

    // -------- conv2 x3 --------
    for (int l = 0; l < 3; l++) {
        mma_gemm<1, 0><<<G2, 256, MM_SMEM>>>(ahi, alo, whi, wlo,
                                             OFF_C2S + l * 16384, OFF_C2D + l * 16384,
                                             nullptr, 0, hshd, 256, 0,
                                             nullptr, nullptr, NN, 128);
        cudaMemsetAsync(aggr, 0, (size_t)NN * 128 * sizeof(float));
        edge_msg_kernel<16, true><<<EGRID, 256>>>(hshd, ei3, ea3, ea4,
                                                  c2We + l * 16 * 128, c2bm + l * 128,
                                                  aggr, 2 * E3N, E3N);
        aconv_kernel<<<(NN * 16 + 255) / 256, 256>>>(aggr, inv2, ahi, alo);
        mma_gemm<0, 1><<<G1, 256, MM_SMEM>>>(ahi, alo, whi, wlo,
                                             OFF_C2U + l * 32768, 0,
                                             c2bu + l * 128, 1, nullptr, 0, 0,
                                             ahi, alo, NN, 256);
    }

    // -------- head --------
    mma_gemm<1, 0><<<G2, 256, MM_SMEM>>>(ahi, alo, whi, wlo,
                                         OFF_HA, OFF_HB,
                                         nullptr, 0, hshd, 256, 0,
                                         nullptr, nullptr, NN, 128);
    head_kernel<<<EGRID, 256>>>(hshd, ei3, ea3, ea4,
                                headW1 + 256 * 128, headb1, headW2, headb2, out);
}